// round 11
// baseline (speedup 1.0000x reference)
#include <cuda_runtime.h>
#include <cstdint>

#define B_ 8
#define T_ 4096
#define D_ 256
#define H_ 256
#define G_ 768              // 3H
#define M_ (B_ * T_)        // 32768
#define CANARY 0x7FC00001u  // NaN pattern; h is always finite

// Scratch (static device allocations only)
// xg layout (scan-permuted): [d][b][t][rank(4)][w(8)][gate(3)][j(8)]
__device__ float g_xg[(size_t)2 * B_ * T_ * G_];
__device__ float g_outc[(size_t)B_ * T_ * 2 * H_];     // [b][t][512]  (fwd | bwd)

typedef unsigned long long ull;

__device__ __forceinline__ uint32_t s2u(const void* p) {
    uint32_t a;
    asm("{ .reg .u64 t; cvta.to.shared.u64 t, %1; cvt.u32.u64 %0, t; }"
        : "=r"(a) : "l"(p));
    return a;
}
__device__ __forceinline__ ull ffma2(ull a, ull b, ull c) {
    ull d;
    asm("fma.rn.f32x2 %0, %1, %2, %3;" : "=l"(d) : "l"(a), "l"(b), "l"(c));
    return d;
}
__device__ __forceinline__ ull fadd2(ull a, ull b) {
    ull d;
    asm("add.rn.f32x2 %0, %1, %2;" : "=l"(d) : "l"(a), "l"(b));
    return d;
}
__device__ __forceinline__ ull pack2(float lo, float hi) {
    ull r;
    asm("mov.b64 %0, {%1, %2};" : "=l"(r)
        : "r"(__float_as_uint(lo)), "r"(__float_as_uint(hi)));
    return r;
}
__device__ __forceinline__ ull pack2u(uint32_t lo, uint32_t hi) {
    ull r;
    asm("mov.b64 %0, {%1, %2};" : "=l"(r) : "r"(lo), "r"(hi));
    return r;
}
__device__ __forceinline__ void unpack2(ull a, float& lo, float& hi) {
    uint32_t l, h;
    asm("mov.b64 {%0, %1}, %2;" : "=r"(l), "=r"(h) : "l"(a));
    lo = __uint_as_float(l); hi = __uint_as_float(h);
}
__device__ __forceinline__ float sum2(ull a) {
    float lo, hi; unpack2(a, lo, hi); return lo + hi;
}
__device__ __forceinline__ float fast_sigmoid(float x) {
    float e, r;
    asm("ex2.approx.f32 %0, %1;" : "=f"(e) : "f"(-1.4426950408889634f * x));
    asm("rcp.approx.f32 %0, %1;" : "=f"(r) : "f"(1.0f + e));
    return r;
}
__device__ __forceinline__ float fast_tanh(float x) {
    float e, r;
    asm("ex2.approx.f32 %0, %1;" : "=f"(e) : "f"(-2.8853900817779268f * x));
    asm("rcp.approx.f32 %0, %1;" : "=f"(r) : "f"(1.0f + e));
    return fmaf(2.0f, r, -1.0f);
}

// ---------------------------------------------------------------------------
// Kernel A: xg[d] = X @ Wi_d + bi_d   X:[32768,256], Wi:[256,768]
// FFMA2 inner loop. Output permuted: col n -> rank*192 + w*24 + gate*8 + j.
// ---------------------------------------------------------------------------
__global__ void __launch_bounds__(256) k_xgemm(
    const float* __restrict__ X,
    const float* __restrict__ Wi_f, const float* __restrict__ bi_f,
    const float* __restrict__ Wi_b, const float* __restrict__ bi_b)
{
    const int d = blockIdx.z;
    const float* W  = d ? Wi_b : Wi_f;
    const float* bi = d ? bi_b : bi_f;
    float* out = g_xg + (size_t)d * M_ * G_;

    const int m0 = blockIdx.y * 128;
    const int n0 = blockIdx.x * 64;

    __shared__ __align__(16) float As[16][136];
    __shared__ __align__(16) ull   Bs2[16][64];

    const int tid = threadIdx.x;
    const int ti = tid >> 4;
    const int tj = tid & 15;

    ull acc2[4][4];
#pragma unroll
    for (int i = 0; i < 4; ++i)
#pragma unroll
        for (int j = 0; j < 4; ++j) acc2[i][j] = 0ull;

    for (int k0 = 0; k0 < D_; k0 += 16) {
#pragma unroll
        for (int p = 0; p < 8; ++p) {
            int idx = tid + p * 256;
            int r = idx >> 4, c = idx & 15;
            As[c][r] = X[(size_t)(m0 + r) * D_ + k0 + c];
        }
#pragma unroll
        for (int p = 0; p < 4; ++p) {
            int idx = tid + p * 256;
            int r = idx >> 6, c = idx & 63;
            float bv = W[(size_t)(k0 + r) * G_ + n0 + c];
            Bs2[r][c] = pack2(bv, bv);
        }
        __syncthreads();
#pragma unroll
        for (int kk = 0; kk < 16; ++kk) {
            ull ap[4];
            const ull* arow = (const ull*)&As[kk][ti * 8];
            ap[0] = arow[0]; ap[1] = arow[1]; ap[2] = arow[2]; ap[3] = arow[3];
            ull bd[4];
            const ull* brow = &Bs2[kk][tj * 4];
            bd[0] = brow[0]; bd[1] = brow[1]; bd[2] = brow[2]; bd[3] = brow[3];
#pragma unroll
            for (int i = 0; i < 4; ++i)
#pragma unroll
                for (int j = 0; j < 4; ++j)
                    acc2[i][j] = ffma2(ap[i], bd[j], acc2[i][j]);
        }
        __syncthreads();
    }

    // permuted store: n -> rank*192 + w*24 + gate*8 + j
    const int n = n0 + tj * 4;
    const int g = n >> 8, u = n & 255;
    const int pos = (u >> 6) * 192 + ((u >> 3) & 7) * 24 + g * 8 + (u & 7);
    float4 bb = *(const float4*)&bi[n];
#pragma unroll
    for (int i = 0; i < 4; ++i) {
        float4 o0, o1;
        unpack2(acc2[i][0], o0.x, o1.x);
        unpack2(acc2[i][1], o0.y, o1.y);
        unpack2(acc2[i][2], o0.z, o1.z);
        unpack2(acc2[i][3], o0.w, o1.w);
        o0.x += bb.x; o0.y += bb.y; o0.z += bb.z; o0.w += bb.w;
        o1.x += bb.x; o1.y += bb.y; o1.z += bb.z; o1.w += bb.w;
        *(float4*)&out[(size_t)(m0 + ti * 8 + i * 2)     * G_ + pos] = o0;
        *(float4*)&out[(size_t)(m0 + ti * 8 + i * 2 + 1) * G_ + pos] = o1;
    }
}

// ---------------------------------------------------------------------------
// Kernel B: 4-CTA clustered bidirectional GRU scan. Warp-autonomous canary
// ring + PHASED dots (own block first, remote blocks consumed on arrival so
// fabric latency overlaps compute). Scalar self-routed sends, direct per-lane
// gi loads, zero shfl broadcasts/gathers on the critical path.
// Lane (ss = lane>>3, j = lane&7): 16 K-values from EACH of the 4 blocks.
// ---------------------------------------------------------------------------
__global__ void __launch_bounds__(256, 1) __cluster_dims__(4, 1, 1)
k_scan(const float* __restrict__ Wh_f, const float* __restrict__ bhn_f,
       const float* __restrict__ Wh_b, const float* __restrict__ bhn_b)
{
    __shared__ __align__(16) float hbuf[4][272];   // 4 blocks x (64 data + 4 pad)
    __shared__ __align__(16) float hist[16][64];   // output staging

    const uint32_t hbuf_a = s2u(hbuf);

    const int rank = blockIdx.x & 3;
    const int cid  = blockIdx.x >> 2;
    const int d    = cid >> 3;
    const int b    = cid & 7;

    const float* Wh  = d ? Wh_b  : Wh_f;
    const float* bhn = d ? bhn_b : bhn_f;

    const int tid  = threadIdx.x;
    const int w    = tid >> 5;
    const int lane = tid & 31;
    const int ss   = lane >> 3;                    // K sub-slot (0..3)
    const int j    = lane & 7;                     // unit within warp (0..7)
    const int unit = rank * 64 + w * 8 + j;

    // ---- W in registers, PHASED layout: phase i covers block (rank+i)&3,
    //      lane's 16 K-values at block*64 + ss*16 .. +16 ----
    ull Wr2[32], Wz2[32], Wn2[32];
#pragma unroll
    for (int i = 0; i < 4; ++i) {
        const int bp = (rank + i) & 3;
#pragma unroll
        for (int m = 0; m < 8; ++m) {
            const int k0 = bp * 64 + ss * 16 + m * 2;
            size_t r0 = (size_t)k0 * G_;
            size_t r1 = r0 + G_;
            Wr2[i * 8 + m] = pack2(__ldg(Wh + r0 + unit),       __ldg(Wh + r1 + unit));
            Wz2[i * 8 + m] = pack2(__ldg(Wh + r0 + 256 + unit), __ldg(Wh + r1 + 256 + unit));
            Wn2[i * 8 + m] = pack2(__ldg(Wh + r0 + 512 + unit), __ldg(Wh + r1 + 512 + unit));
        }
    }

    // init: buf0 = h0 = 0, buf1..3 = canary
    for (int i = tid; i < 272; i += 256) {
        hbuf[0][i] = 0.f;
        ((unsigned*)hbuf[1])[i] = CANARY;
        ((unsigned*)hbuf[2])[i] = CANARY;
        ((unsigned*)hbuf[3])[i] = CANARY;
    }
    __syncthreads();
    asm volatile("barrier.cluster.arrive.aligned;" ::: "memory");
    asm volatile("barrier.cluster.wait.aligned;"   ::: "memory");

    // scalar self-routed send: lane delivers its own unit j to peer (rank+ss)&3
    uint32_t sdata;
    {
        uint32_t peer = (uint32_t)((rank + ss) & 3);
        uint32_t rhb;
        asm("mapa.shared::cluster.u32 %0, %1, %2;" : "=r"(rhb) : "r"(hbuf_a), "r"(peer));
        sdata = rhb + (uint32_t)(rank * 68 + w * 8 + j) * 4;
    }

    // phase poll/data addresses (16 words per lane per phase)
    uint32_t pa[4];
#pragma unroll
    for (int i = 0; i < 4; ++i)
        pa[i] = hbuf_a + (uint32_t)(((rank + i) & 3) * 68 + ss * 16) * 4;

    // re-canary partition: warp w owns block (w>>1), half (w&1), word lane
    const uint32_t ca = hbuf_a + (uint32_t)((w >> 1) * 272 + (w & 1) * 128 + lane * 4);

    const float bhn_u = bhn[unit];
    const float* xgq = g_xg + ((size_t)(d * B_ + b)) * T_ * G_ + rank * 192 + w * 24;

    // 3-deep per-lane gi ring (each lane loads its OWN 3 gate values)
    float gr0, gr1, gr2, gz0, gz1, gz2, gn0, gn1, gn2;
    {
        const int t0 = d ? T_ - 1 : 0;
        const int t1 = d ? T_ - 2 : 1;
        const int t2 = d ? T_ - 3 : 2;
        gr0 = __ldg(xgq + (size_t)t0 * G_ + j);
        gz0 = __ldg(xgq + (size_t)t0 * G_ + 8 + j);
        gn0 = __ldg(xgq + (size_t)t0 * G_ + 16 + j);
        gr1 = __ldg(xgq + (size_t)t1 * G_ + j);
        gz1 = __ldg(xgq + (size_t)t1 * G_ + 8 + j);
        gn1 = __ldg(xgq + (size_t)t1 * G_ + 16 + j);
        gr2 = __ldg(xgq + (size_t)t2 * G_ + j);
        gz2 = __ldg(xgq + (size_t)t2 * G_ + 8 + j);
        gn2 = __ldg(xgq + (size_t)t2 * G_ + 16 + j);
    }

    float hprev = 0.f;

    for (int s = 0; s < T_; ++s) {
        const uint32_t qoff = (uint32_t)(s & 3) * 1088;

        // ---- re-canary buf (s+2)&3 (provably dead; see causality proof) ----
        asm volatile("st.shared.u32 [%0], %1;"
                     :: "r"(ca + (uint32_t)((s + 2) & 3) * 1088), "r"(CANARY)
                     : "memory");

        // ---- phased poll + dots: block (rank+i)&3 consumed as it arrives ----
        ull ar0 = 0, ar1 = 0, az0 = 0, az1 = 0, an0 = 0, an1 = 0;
#pragma unroll
        for (int i = 0; i < 4; ++i) {
            const uint32_t a = pa[i] + qoff;
            uint32_t hx0, hx1, hx2, hx3, hx4, hx5, hx6, hx7;
            uint32_t hx8, hx9, hxA, hxB, hxC, hxD, hxE, hxF;
            for (;;) {
                asm volatile("ld.volatile.shared.v4.u32 {%0,%1,%2,%3}, [%4];"
                             : "=r"(hx0), "=r"(hx1), "=r"(hx2), "=r"(hx3) : "r"(a));
                asm volatile("ld.volatile.shared.v4.u32 {%0,%1,%2,%3}, [%4];"
                             : "=r"(hx4), "=r"(hx5), "=r"(hx6), "=r"(hx7) : "r"(a + 16));
                asm volatile("ld.volatile.shared.v4.u32 {%0,%1,%2,%3}, [%4];"
                             : "=r"(hx8), "=r"(hx9), "=r"(hxA), "=r"(hxB) : "r"(a + 32));
                asm volatile("ld.volatile.shared.v4.u32 {%0,%1,%2,%3}, [%4];"
                             : "=r"(hxC), "=r"(hxD), "=r"(hxE), "=r"(hxF) : "r"(a + 48));
                bool bad = (hx0 == CANARY) | (hx1 == CANARY) | (hx2 == CANARY) |
                           (hx3 == CANARY) | (hx4 == CANARY) | (hx5 == CANARY) |
                           (hx6 == CANARY) | (hx7 == CANARY) | (hx8 == CANARY) |
                           (hx9 == CANARY) | (hxA == CANARY) | (hxB == CANARY) |
                           (hxC == CANARY) | (hxD == CANARY) | (hxE == CANARY) |
                           (hxF == CANARY);
                if (!__any_sync(0xFFFFFFFFu, bad)) break;
            }
            ull hp0 = pack2u(hx0, hx1), hp1 = pack2u(hx2, hx3);
            ull hp2 = pack2u(hx4, hx5), hp3 = pack2u(hx6, hx7);
            ull hp4 = pack2u(hx8, hx9), hp5 = pack2u(hxA, hxB);
            ull hp6 = pack2u(hxC, hxD), hp7 = pack2u(hxE, hxF);
            ar0 = ffma2(Wr2[i * 8 + 0], hp0, ar0);
            ar1 = ffma2(Wr2[i * 8 + 1], hp1, ar1);
            az0 = ffma2(Wz2[i * 8 + 0], hp0, az0);
            az1 = ffma2(Wz2[i * 8 + 1], hp1, az1);
            an0 = ffma2(Wn2[i * 8 + 0], hp0, an0);
            an1 = ffma2(Wn2[i * 8 + 1], hp1, an1);
            ar0 = ffma2(Wr2[i * 8 + 2], hp2, ar0);
            ar1 = ffma2(Wr2[i * 8 + 3], hp3, ar1);
            az0 = ffma2(Wz2[i * 8 + 2], hp2, az0);
            az1 = ffma2(Wz2[i * 8 + 3], hp3, az1);
            an0 = ffma2(Wn2[i * 8 + 2], hp2, an0);
            an1 = ffma2(Wn2[i * 8 + 3], hp3, an1);
            ar0 = ffma2(Wr2[i * 8 + 4], hp4, ar0);
            ar1 = ffma2(Wr2[i * 8 + 5], hp5, ar1);
            az0 = ffma2(Wz2[i * 8 + 4], hp4, az0);
            az1 = ffma2(Wz2[i * 8 + 5], hp5, az1);
            an0 = ffma2(Wn2[i * 8 + 4], hp4, an0);
            an1 = ffma2(Wn2[i * 8 + 5], hp5, an1);
            ar0 = ffma2(Wr2[i * 8 + 6], hp6, ar0);
            ar1 = ffma2(Wr2[i * 8 + 7], hp7, ar1);
            az0 = ffma2(Wz2[i * 8 + 6], hp6, az0);
            az1 = ffma2(Wz2[i * 8 + 7], hp7, az1);
            an0 = ffma2(Wn2[i * 8 + 6], hp6, an0);
            an1 = ffma2(Wn2[i * 8 + 7], hp7, an1);
        }

        float sr = sum2(fadd2(ar0, ar1));
        float sz = sum2(fadd2(az0, az1));
        float sn = sum2(fadd2(an0, an1));
        // interleaved xor-reduce over ss (lanes differing in bits 3,4)
        sr += __shfl_xor_sync(0xFFFFFFFFu, sr, 8);
        sz += __shfl_xor_sync(0xFFFFFFFFu, sz, 8);
        sn += __shfl_xor_sync(0xFFFFFFFFu, sn, 8);
        sr += __shfl_xor_sync(0xFFFFFFFFu, sr, 16);
        sz += __shfl_xor_sync(0xFFFFFFFFu, sz, 16);
        sn += __shfl_xor_sync(0xFFFFFFFFu, sn, 16);

        {
            float r = fast_sigmoid(gr0 + sr);
            float z = fast_sigmoid(gz0 + sz);
            float n = fast_tanh(fmaf(r, sn + bhn_u, gn0));
            hprev = fmaf(z, hprev - n, n);          // h_new (all lanes, own j)
        }

        // ---- send: every lane self-routes its unit to peer (rank+ss)&3 ----
        if (s + 1 < T_) {
            asm volatile("st.shared::cluster.u32 [%0], %1;"
                         :: "r"(sdata + (uint32_t)((s + 1) & 3) * 1088),
                            "r"(__float_as_uint(hprev)) : "memory");
            // advance gi ring (prefetch s+3)
            gr0 = gr1; gr1 = gr2;
            gz0 = gz1; gz1 = gz2;
            gn0 = gn1; gn1 = gn2;
            if (s + 3 < T_) {
                const int tn = d ? (T_ - 4 - s) : (s + 3);
                gr2 = __ldg(xgq + (size_t)tn * G_ + j);
                gz2 = __ldg(xgq + (size_t)tn * G_ + 8 + j);
                gn2 = __ldg(xgq + (size_t)tn * G_ + 16 + j);
            }
        }

        // ---- stage output ----
        if (lane < 8) hist[s & 15][w * 8 + lane] = hprev;

        // ---- skew-safe flush: rows [s-14, s-7] ----
        if ((s & 7) == 7) {
            const int rr = s - 14 + w;
            if (rr >= 0) {
                const int tw = d ? (T_ - 1 - rr) : rr;
                *(float2*)&g_outc[((size_t)b * T_ + tw) * 512 + d * 256 +
                                  rank * 64 + lane * 2] =
                    *(const float2*)&hist[rr & 15][lane * 2];
            }
        }
    }

    // tail: rows 4089..4095 (warps 1..7), after all warps finish
    __syncthreads();
    if (w >= 1) {
        const int rr = 4088 + w;
        const int tw = d ? (T_ - 1 - rr) : rr;
        *(float2*)&g_outc[((size_t)b * T_ + tw) * 512 + d * 256 +
                          rank * 64 + lane * 2] =
            *(const float2*)&hist[rr & 15][lane * 2];
    }

    // no CTA may exit while peers can still write its smem
    asm volatile("barrier.cluster.arrive.aligned;" ::: "memory");
    asm volatile("barrier.cluster.wait.aligned;"   ::: "memory");
}

// ---------------------------------------------------------------------------
// Kernel C: heads. out_combined [32768,512] @ (Wm|Wv) [512,256] + bias. FFMA2.
// ---------------------------------------------------------------------------
__global__ void __launch_bounds__(256) k_heads(
    const float* __restrict__ Wm, const float* __restrict__ bm,
    const float* __restrict__ Wv, const float* __restrict__ bv,
    float* __restrict__ out)
{
    const int n0 = blockIdx.x * 64;
    const int m0 = blockIdx.y * 128;
    const bool isV = (n0 >= 256);
    const float* W  = isV ? Wv : Wm;
    const float* bb = isV ? bv : bm;
    const int nw = n0 & 255;

    __shared__ __align__(16) float As[16][136];
    __shared__ __align__(16) ull   Bs2[16][64];

    const int tid = threadIdx.x;
    const int ti = tid >> 4, tj = tid & 15;

    ull acc2[4][4];
#pragma unroll
    for (int i = 0; i < 4; ++i)
#pragma unroll
        for (int j = 0; j < 4; ++j) acc2[i][j] = 0ull;

    for (int k0 = 0; k0 < 512; k0 += 16) {
#pragma unroll
        for (int p = 0; p < 8; ++p) {
            int idx = tid + p * 256;
            int r = idx >> 4, c = idx & 15;
            As[c][r] = g_outc[(size_t)(m0 + r) * 512 + k0 + c];
        }
#pragma unroll
        for (int p = 0; p < 4; ++p) {
            int idx = tid + p * 256;
            int r = idx >> 6, c = idx & 63;
            float bv2 = W[(size_t)(k0 + r) * 256 + nw + c];
            Bs2[r][c] = pack2(bv2, bv2);
        }
        __syncthreads();
#pragma unroll
        for (int kk = 0; kk < 16; ++kk) {
            ull ap[4];
            const ull* arow = (const ull*)&As[kk][ti * 8];
            ap[0] = arow[0]; ap[1] = arow[1]; ap[2] = arow[2]; ap[3] = arow[3];
            ull bd[4];
            const ull* brow = &Bs2[kk][tj * 4];
            bd[0] = brow[0]; bd[1] = brow[1]; bd[2] = brow[2]; bd[3] = brow[3];
#pragma unroll
            for (int i = 0; i < 4; ++i)
#pragma unroll
                for (int jj = 0; jj < 4; ++jj)
                    acc2[i][jj] = ffma2(ap[i], bd[jj], acc2[i][jj]);
        }
        __syncthreads();
    }

    const size_t hofs = (size_t)M_ * H_;
    float4 bb4 = *(const float4*)&bb[nw + tj * 4];
#pragma unroll
    for (int i = 0; i < 4; ++i) {
        float4 o0, o1;
        unpack2(acc2[i][0], o0.x, o1.x);
        unpack2(acc2[i][1], o0.y, o1.y);
        unpack2(acc2[i][2], o0.z, o1.z);
        unpack2(acc2[i][3], o0.w, o1.w);
        o0.x += bb4.x; o0.y += bb4.y; o0.z += bb4.z; o0.w += bb4.w;
        o1.x += bb4.x; o1.y += bb4.y; o1.z += bb4.z; o1.w += bb4.w;
        int r0 = m0 + ti * 8 + i * 2, r1 = r0 + 1;
        if (isV) {
            o0.x = expf(o0.x); o0.y = expf(o0.y); o0.z = expf(o0.z); o0.w = expf(o0.w);
            o1.x = expf(o1.x); o1.y = expf(o1.y); o1.z = expf(o1.z); o1.w = expf(o1.w);
            *(float4*)&out[(size_t)r0 * 256 + nw + tj * 4] = o0;
            *(float4*)&out[(size_t)r1 * 256 + nw + tj * 4] = o1;
        } else {
            *(float4*)&out[hofs + (size_t)r0 * 256 + nw + tj * 4] = o0;
            *(float4*)&out[hofs + (size_t)r1 * 256 + nw + tj * 4] = o1;
        }
    }
}

// ---------------------------------------------------------------------------
extern "C" void kernel_launch(void* const* d_in, const int* in_sizes, int n_in,
                              void* d_out, int out_size)
{
    const float* inputs = (const float*)d_in[0];
    const float* Wi_f   = (const float*)d_in[1];
    const float* bi_f   = (const float*)d_in[2];
    const float* Wh_f   = (const float*)d_in[3];
    const float* bhn_f  = (const float*)d_in[4];
    const float* Wi_b   = (const float*)d_in[5];
    const float* bi_b   = (const float*)d_in[6];
    const float* Wh_b   = (const float*)d_in[7];
    const float* bhn_b  = (const float*)d_in[8];
    const float* Wm     = (const float*)d_in[9];
    const float* bm     = (const float*)d_in[10];
    const float* Wv     = (const float*)d_in[11];
    const float* bv     = (const float*)d_in[12];
    float* out = (float*)d_out;

    (void)in_sizes; (void)n_in; (void)out_size;

    k_xgemm<<<dim3(12, 256, 2), 256>>>(inputs, Wi_f, bi_f, Wi_b, bi_b);
    k_scan<<<64, 256>>>(Wh_f, bhn_f, Wh_b, bhn_b);
    k_heads<<<dim3(8, 256), 256>>>(Wm, bm, Wv, bv, out);
}

// round 12
// speedup vs baseline: 1.3444x; 1.3444x over previous
#include <cuda_runtime.h>
#include <cstdint>

#define B_ 8
#define T_ 4096
#define D_ 256
#define H_ 256
#define G_ 768              // 3H
#define M_ (B_ * T_)        // 32768
#define CANARY 0x7FC00001u  // NaN pattern; h is always finite

// Scratch (static device allocations only)
// xg layout (scan-permuted): [d][b][t][rank(4)][w(8)][gate(3)][j(8)]
__device__ float g_xg[(size_t)2 * B_ * T_ * G_];
__device__ float g_outc[(size_t)B_ * T_ * 2 * H_];     // [b][t][512]  (fwd | bwd)

typedef unsigned long long ull;

__device__ __forceinline__ uint32_t s2u(const void* p) {
    uint32_t a;
    asm("{ .reg .u64 t; cvta.to.shared.u64 t, %1; cvt.u32.u64 %0, t; }"
        : "=r"(a) : "l"(p));
    return a;
}
__device__ __forceinline__ ull ffma2(ull a, ull b, ull c) {
    ull d;
    asm("fma.rn.f32x2 %0, %1, %2, %3;" : "=l"(d) : "l"(a), "l"(b), "l"(c));
    return d;
}
__device__ __forceinline__ ull fadd2(ull a, ull b) {
    ull d;
    asm("add.rn.f32x2 %0, %1, %2;" : "=l"(d) : "l"(a), "l"(b));
    return d;
}
__device__ __forceinline__ ull pack2(float lo, float hi) {
    ull r;
    asm("mov.b64 %0, {%1, %2};" : "=l"(r)
        : "r"(__float_as_uint(lo)), "r"(__float_as_uint(hi)));
    return r;
}
__device__ __forceinline__ ull dup2(float v) {
    ull r;
    asm("mov.b64 %0, {%1, %1};" : "=l"(r) : "r"(__float_as_uint(v)));
    return r;
}
__device__ __forceinline__ void unpack2(ull a, float& lo, float& hi) {
    uint32_t l, h;
    asm("mov.b64 {%0, %1}, %2;" : "=r"(l), "=r"(h) : "l"(a));
    lo = __uint_as_float(l); hi = __uint_as_float(h);
}
__device__ __forceinline__ float sum2(ull a) {
    float lo, hi; unpack2(a, lo, hi); return lo + hi;
}
__device__ __forceinline__ float fast_sigmoid(float x) {
    float e, r;
    asm("ex2.approx.f32 %0, %1;" : "=f"(e) : "f"(-1.4426950408889634f * x));
    asm("rcp.approx.f32 %0, %1;" : "=f"(r) : "f"(1.0f + e));
    return r;
}
__device__ __forceinline__ float fast_tanh(float x) {
    float e, r;
    asm("ex2.approx.f32 %0, %1;" : "=f"(e) : "f"(-2.8853900817779268f * x));
    asm("rcp.approx.f32 %0, %1;" : "=f"(r) : "f"(1.0f + e));
    return fmaf(2.0f, r, -1.0f);
}

// ---------------------------------------------------------------------------
// Kernel A: xg[d] = X @ Wi_d + bi_d   X:[32768,256], Wi:[256,768]
// FFMA2, B stored NON-duplicated (float) in smem; pair-duplication done in
// registers on the ALU pipe. Output permuted to scan layout.
// ---------------------------------------------------------------------------
__global__ void __launch_bounds__(256) k_xgemm(
    const float* __restrict__ X,
    const float* __restrict__ Wi_f, const float* __restrict__ bi_f,
    const float* __restrict__ Wi_b, const float* __restrict__ bi_b)
{
    const int d = blockIdx.z;
    const float* W  = d ? Wi_b : Wi_f;
    const float* bi = d ? bi_b : bi_f;
    float* out = g_xg + (size_t)d * M_ * G_;

    const int m0 = blockIdx.y * 128;
    const int n0 = blockIdx.x * 64;

    __shared__ __align__(16) float As[16][136];   // [k][m]
    __shared__ __align__(16) float Bs[16][68];    // [k][n], NOT duplicated

    const int tid = threadIdx.x;
    const int ti = tid >> 4;        // 8 rows (4 row-pairs)
    const int tj = tid & 15;        // 4 cols

    ull acc2[4][4];
#pragma unroll
    for (int i = 0; i < 4; ++i)
#pragma unroll
        for (int j = 0; j < 4; ++j) acc2[i][j] = 0ull;

    for (int k0 = 0; k0 < D_; k0 += 16) {
#pragma unroll
        for (int p = 0; p < 8; ++p) {
            int idx = tid + p * 256;
            int r = idx >> 4, c = idx & 15;
            As[c][r] = X[(size_t)(m0 + r) * D_ + k0 + c];
        }
#pragma unroll
        for (int p = 0; p < 4; ++p) {
            int idx = tid + p * 256;
            int r = idx >> 6, c = idx & 63;
            Bs[r][c] = W[(size_t)(k0 + r) * G_ + n0 + c];
        }
        __syncthreads();
#pragma unroll
        for (int kk = 0; kk < 16; ++kk) {
            ull ap[4];
            const ull* arow = (const ull*)&As[kk][ti * 8];
            ap[0] = arow[0]; ap[1] = arow[1]; ap[2] = arow[2]; ap[3] = arow[3];
            float4 bq = *(const float4*)&Bs[kk][tj * 4];    // 16B, conflict-free
            ull bd[4];
            bd[0] = dup2(bq.x); bd[1] = dup2(bq.y);
            bd[2] = dup2(bq.z); bd[3] = dup2(bq.w);
#pragma unroll
            for (int i = 0; i < 4; ++i)
#pragma unroll
                for (int j = 0; j < 4; ++j)
                    acc2[i][j] = ffma2(ap[i], bd[j], acc2[i][j]);
        }
        __syncthreads();
    }

    // permuted store: n -> rank*192 + w*24 + gate*8 + j
    const int n = n0 + tj * 4;
    const int g = n >> 8, u = n & 255;
    const int pos = (u >> 6) * 192 + ((u >> 3) & 7) * 24 + g * 8 + (u & 7);
    float4 bb = *(const float4*)&bi[n];
#pragma unroll
    for (int i = 0; i < 4; ++i) {
        float4 o0, o1;
        unpack2(acc2[i][0], o0.x, o1.x);
        unpack2(acc2[i][1], o0.y, o1.y);
        unpack2(acc2[i][2], o0.z, o1.z);
        unpack2(acc2[i][3], o0.w, o1.w);
        o0.x += bb.x; o0.y += bb.y; o0.z += bb.z; o0.w += bb.w;
        o1.x += bb.x; o1.y += bb.y; o1.z += bb.z; o1.w += bb.w;
        *(float4*)&out[(size_t)(m0 + ti * 8 + i * 2)     * G_ + pos] = o0;
        *(float4*)&out[(size_t)(m0 + ti * 8 + i * 2 + 1) * G_ + pos] = o1;
    }
}

// ---------------------------------------------------------------------------
// Kernel B: 4-CTA clustered bidirectional GRU scan. (Round-10 version — the
// best measured.) Warp-autonomous 4-buffer canary ring, no __syncthreads in
// the loop, per-warp coalesced 16B sends to all 4 CTAs.
// ---------------------------------------------------------------------------
__global__ void __launch_bounds__(256, 1) __cluster_dims__(4, 1, 1)
k_scan(const float* __restrict__ Wh_f, const float* __restrict__ bhn_f,
       const float* __restrict__ Wh_b, const float* __restrict__ bhn_b)
{
    __shared__ __align__(16) float hbuf[4][272];   // 4 blocks x (64 data + 4 pad)
    __shared__ __align__(16) float hist[16][64];   // output staging

    const uint32_t hbuf_a = s2u(hbuf);

    const int rank = blockIdx.x & 3;
    const int cid  = blockIdx.x >> 2;
    const int d    = cid >> 3;
    const int b    = cid & 7;

    const float* Wh  = d ? Wh_b  : Wh_f;
    const float* bhn = d ? bhn_b : bhn_f;

    const int tid  = threadIdx.x;
    const int w    = tid >> 5;
    const int lane = tid & 31;
    const int kq   = lane >> 3;                    // K-chunk of 64 (0..3)
    const int j    = lane & 7;                     // unit within warp (0..7)
    const int unit = rank * 64 + w * 8 + j;

    // ---- W slice fully in registers: 96 b64 per lane ----
    ull Wr2[32], Wz2[32], Wn2[32];
#pragma unroll
    for (int kk = 0; kk < 32; ++kk) {
        size_t r0 = (size_t)(kq * 64 + kk * 2) * G_;
        size_t r1 = r0 + G_;
        Wr2[kk] = pack2(__ldg(Wh + r0 + unit),       __ldg(Wh + r1 + unit));
        Wz2[kk] = pack2(__ldg(Wh + r0 + 256 + unit), __ldg(Wh + r1 + 256 + unit));
        Wn2[kk] = pack2(__ldg(Wh + r0 + 512 + unit), __ldg(Wh + r1 + 512 + unit));
    }

    // init: buf0 = h0 = 0, buf1..3 = canary
    for (int i = tid; i < 272; i += 256) {
        hbuf[0][i] = 0.f;
        ((unsigned*)hbuf[1])[i] = CANARY;
        ((unsigned*)hbuf[2])[i] = CANARY;
        ((unsigned*)hbuf[3])[i] = CANARY;
    }
    __syncthreads();
    asm volatile("barrier.cluster.arrive.aligned;" ::: "memory");
    asm volatile("barrier.cluster.wait.aligned;"   ::: "memory");

    // send address (lanes 0..7): peer = (rank + (lane>>1)) & 3 (incl. self),
    // half = lane&1. Warp w's 8 units live at words rank*68 + w*8 (+half*4).
    uint32_t sdata = 0;
    if (lane < 8) {
        uint32_t peer = (uint32_t)((rank + (lane >> 1)) & 3);
        uint32_t rhb;
        asm("mapa.shared::cluster.u32 %0, %1, %2;" : "=r"(rhb) : "r"(hbuf_a), "r"(peer));
        sdata = rhb + (uint32_t)(rank * 272 + w * 32 + (lane & 1) * 16);
    }

    // poll address: lane waits on producer warp j of CTA kq (8 words, 2 v4)
    const uint32_t pa = hbuf_a + (uint32_t)(kq * 272 + j * 32);
    // re-canary partition: warp w owns block (w>>1), half (w&1), word lane
    const uint32_t ca = hbuf_a + (uint32_t)((w >> 1) * 272 + (w & 1) * 128 + lane * 4);

    const float bhn_u = bhn[unit];
    const float* xgp = g_xg + ((size_t)(d * B_ + b)) * T_ * G_ + rank * 192 + w * 24;

    // 3-deep gi prefetch ring (lanes 0..23: gate = lane>>3, j = lane&7)
    float gv0 = 0.f, gv1 = 0.f, gv2 = 0.f;
    if (lane < 24) {
        gv0 = __ldg(xgp + (size_t)(d ? T_ - 1 : 0) * G_ + lane);
        gv1 = __ldg(xgp + (size_t)(d ? T_ - 2 : 1) * G_ + lane);
        gv2 = __ldg(xgp + (size_t)(d ? T_ - 3 : 2) * G_ + lane);
    }

    float hprev = 0.f;

    for (int s = 0; s < T_; ++s) {
        const int q = s & 3;

        // ---- 1. poll: this lane's producer-warp words present ----
        {
            const uint32_t a = pa + (uint32_t)q * 1088;
            for (;;) {
                uint32_t x0, x1, x2, x3, y0, y1, y2, y3;
                asm volatile("ld.volatile.shared.v4.u32 {%0,%1,%2,%3}, [%4];"
                             : "=r"(x0), "=r"(x1), "=r"(x2), "=r"(x3) : "r"(a));
                asm volatile("ld.volatile.shared.v4.u32 {%0,%1,%2,%3}, [%4];"
                             : "=r"(y0), "=r"(y1), "=r"(y2), "=r"(y3) : "r"(a + 16));
                bool bad = (x0 == CANARY) | (x1 == CANARY) | (x2 == CANARY) |
                           (x3 == CANARY) | (y0 == CANARY) | (y1 == CANARY) |
                           (y2 == CANARY) | (y3 == CANARY);
                if (!__any_sync(0xFFFFFFFFu, bad)) break;
            }
        }

        // ---- 2. re-canary buf (q+2)&3 (read-complete: all warps >= s-1) ----
        {
            const uint32_t a = ca + (uint32_t)((q + 2) & 3) * 1088;
            asm volatile("st.shared.u32 [%0], %1;" :: "r"(a), "r"(CANARY) : "memory");
        }

        // ---- 3. dots: this lane's 64-K chunk (block kq) ----
        const float* hp = &hbuf[q][kq * 68];
        ull ar0 = 0, ar1 = 0, az0 = 0, az1 = 0, an0 = 0, an1 = 0;
#pragma unroll
        for (int qq = 0; qq < 16; ++qq) {
            ulonglong2 hv2 = *(const ulonglong2*)(hp + qq * 4);
            ar0 = ffma2(Wr2[qq * 2],     hv2.x, ar0);
            ar1 = ffma2(Wr2[qq * 2 + 1], hv2.y, ar1);
            az0 = ffma2(Wz2[qq * 2],     hv2.x, az0);
            az1 = ffma2(Wz2[qq * 2 + 1], hv2.y, az1);
            an0 = ffma2(Wn2[qq * 2],     hv2.x, an0);
            an1 = ffma2(Wn2[qq * 2 + 1], hv2.y, an1);
        }
        float sr = sum2(fadd2(ar0, ar1));
        float sz = sum2(fadd2(az0, az1));
        float sn = sum2(fadd2(an0, an1));
#pragma unroll
        for (int m = 8; m <= 16; m <<= 1) {        // reduce over kq
            sr += __shfl_xor_sync(0xFFFFFFFFu, sr, m);
            sz += __shfl_xor_sync(0xFFFFFFFFu, sz, m);
            sn += __shfl_xor_sync(0xFFFFFFFFu, sn, m);
        }

        float gr = __shfl_sync(0xFFFFFFFFu, gv0, j);
        float gz = __shfl_sync(0xFFFFFFFFu, gv0, 8 + j);
        float gn = __shfl_sync(0xFFFFFFFFu, gv0, 16 + j);

        {
            float r = fast_sigmoid(gr + sr);
            float z = fast_sigmoid(gz + sz);
            float n = fast_tanh(fmaf(r, sn + bhn_u, gn));
            hprev = fmaf(z, hprev - n, n);          // h_new, all lanes
        }

        // ---- 4. send: warp's 8 units to all 4 CTAs (8 lanes x 1 v4) ----
        if (s + 1 < T_) {
            const uint32_t qoff = (uint32_t)((s + 1) & 3) * 1088;
            const int base = (lane & 1) * 4;
            float4 v;
            v.x = __shfl_sync(0xFFFFFFFFu, hprev, base + 0);
            v.y = __shfl_sync(0xFFFFFFFFu, hprev, base + 1);
            v.z = __shfl_sync(0xFFFFFFFFu, hprev, base + 2);
            v.w = __shfl_sync(0xFFFFFFFFu, hprev, base + 3);
            if (lane < 8) {
                asm volatile("st.shared::cluster.v4.b32 [%0], {%1, %2, %3, %4};"
                             :: "r"(sdata + qoff),
                                "r"(__float_as_uint(v.x)), "r"(__float_as_uint(v.y)),
                                "r"(__float_as_uint(v.z)), "r"(__float_as_uint(v.w))
                             : "memory");
            }
            // advance gi ring (prefetch s+3)
            gv0 = gv1; gv1 = gv2;
            if (lane < 24 && s + 3 < T_) {
                const int tn = d ? (T_ - 4 - s) : (s + 3);
                gv2 = __ldg(xgp + (size_t)tn * G_ + lane);
            }
        }

        // ---- 5. stage output ----
        if (lane < 8) hist[s & 15][w * 8 + lane] = hprev;

        // ---- 6. skew-safe flush: rows [s-14, s-7] (all provably written) ----
        if ((s & 7) == 7) {
            const int rr = s - 14 + w;
            if (rr >= 0) {
                const int tw = d ? (T_ - 1 - rr) : rr;
                *(float2*)&g_outc[((size_t)b * T_ + tw) * 512 + d * 256 +
                                  rank * 64 + lane * 2] =
                    *(const float2*)&hist[rr & 15][lane * 2];
            }
        }
    }

    // tail: rows 4089..4095 (warps 1..7), after all warps finish
    __syncthreads();
    if (w >= 1) {
        const int rr = 4088 + w;
        const int tw = d ? (T_ - 1 - rr) : rr;
        *(float2*)&g_outc[((size_t)b * T_ + tw) * 512 + d * 256 +
                          rank * 64 + lane * 2] =
            *(const float2*)&hist[rr & 15][lane * 2];
    }

    // no CTA may exit while peers can still write its smem
    asm volatile("barrier.cluster.arrive.aligned;" ::: "memory");
    asm volatile("barrier.cluster.wait.aligned;"   ::: "memory");
}

// ---------------------------------------------------------------------------
// Kernel C: heads. out_combined [32768,512] @ (Wm|Wv) [512,256] + bias.
// FFMA2, non-duplicated B in smem (register duplication).
// ---------------------------------------------------------------------------
__global__ void __launch_bounds__(256) k_heads(
    const float* __restrict__ Wm, const float* __restrict__ bm,
    const float* __restrict__ Wv, const float* __restrict__ bv,
    float* __restrict__ out)
{
    const int n0 = blockIdx.x * 64;
    const int m0 = blockIdx.y * 128;
    const bool isV = (n0 >= 256);
    const float* W  = isV ? Wv : Wm;
    const float* bb = isV ? bv : bm;
    const int nw = n0 & 255;

    __shared__ __align__(16) float As[16][136];
    __shared__ __align__(16) float Bs[16][68];

    const int tid = threadIdx.x;
    const int ti = tid >> 4, tj = tid & 15;

    ull acc2[4][4];
#pragma unroll
    for (int i = 0; i < 4; ++i)
#pragma unroll
        for (int j = 0; j < 4; ++j) acc2[i][j] = 0ull;

    for (int k0 = 0; k0 < 512; k0 += 16) {
#pragma unroll
        for (int p = 0; p < 8; ++p) {
            int idx = tid + p * 256;
            int r = idx >> 4, c = idx & 15;
            As[c][r] = g_outc[(size_t)(m0 + r) * 512 + k0 + c];
        }
#pragma unroll
        for (int p = 0; p < 4; ++p) {
            int idx = tid + p * 256;
            int r = idx >> 6, c = idx & 63;
            Bs[r][c] = W[(size_t)(k0 + r) * 256 + nw + c];
        }
        __syncthreads();
#pragma unroll
        for (int kk = 0; kk < 16; ++kk) {
            ull ap[4];
            const ull* arow = (const ull*)&As[kk][ti * 8];
            ap[0] = arow[0]; ap[1] = arow[1]; ap[2] = arow[2]; ap[3] = arow[3];
            float4 bq = *(const float4*)&Bs[kk][tj * 4];
            ull bd[4];
            bd[0] = dup2(bq.x); bd[1] = dup2(bq.y);
            bd[2] = dup2(bq.z); bd[3] = dup2(bq.w);
#pragma unroll
            for (int i = 0; i < 4; ++i)
#pragma unroll
                for (int jj = 0; jj < 4; ++jj)
                    acc2[i][jj] = ffma2(ap[i], bd[jj], acc2[i][jj]);
        }
        __syncthreads();
    }

    const size_t hofs = (size_t)M_ * H_;
    float4 bb4 = *(const float4*)&bb[nw + tj * 4];
#pragma unroll
    for (int i = 0; i < 4; ++i) {
        float4 o0, o1;
        unpack2(acc2[i][0], o0.x, o1.x);
        unpack2(acc2[i][1], o0.y, o1.y);
        unpack2(acc2[i][2], o0.z, o1.z);
        unpack2(acc2[i][3], o0.w, o1.w);
        o0.x += bb4.x; o0.y += bb4.y; o0.z += bb4.z; o0.w += bb4.w;
        o1.x += bb4.x; o1.y += bb4.y; o1.z += bb4.z; o1.w += bb4.w;
        int r0 = m0 + ti * 8 + i * 2, r1 = r0 + 1;
        if (isV) {
            o0.x = expf(o0.x); o0.y = expf(o0.y); o0.z = expf(o0.z); o0.w = expf(o0.w);
            o1.x = expf(o1.x); o1.y = expf(o1.y); o1.z = expf(o1.z); o1.w = expf(o1.w);
            *(float4*)&out[(size_t)r0 * 256 + nw + tj * 4] = o0;
            *(float4*)&out[(size_t)r1 * 256 + nw + tj * 4] = o1;
        } else {
            *(float4*)&out[hofs + (size_t)r0 * 256 + nw + tj * 4] = o0;
            *(float4*)&out[hofs + (size_t)r1 * 256 + nw + tj * 4] = o1;
        }
    }
}

// ---------------------------------------------------------------------------
extern "C" void kernel_launch(void* const* d_in, const int* in_sizes, int n_in,
                              void* d_out, int out_size)
{
    const float* inputs = (const float*)d_in[0];
    const float* Wi_f   = (const float*)d_in[1];
    const float* bi_f   = (const float*)d_in[2];
    const float* Wh_f   = (const float*)d_in[3];
    const float* bhn_f  = (const float*)d_in[4];
    const float* Wi_b   = (const float*)d_in[5];
    const float* bi_b   = (const float*)d_in[6];
    const float* Wh_b   = (const float*)d_in[7];
    const float* bhn_b  = (const float*)d_in[8];
    const float* Wm     = (const float*)d_in[9];
    const float* bm     = (const float*)d_in[10];
    const float* Wv     = (const float*)d_in[11];
    const float* bv     = (const float*)d_in[12];
    float* out = (float*)d_out;

    (void)in_sizes; (void)n_in; (void)out_size;

    k_xgemm<<<dim3(12, 256, 2), 256>>>(inputs, Wi_f, bi_f, Wi_b, bi_b);
    k_scan<<<64, 256>>>(Wh_f, bhn_f, Wh_b, bhn_b);
    k_heads<<<dim3(8, 256), 256>>>(Wm, bm, Wv, bv, out);
}

// round 13
// speedup vs baseline: 1.3785x; 1.0254x over previous
#include <cuda_runtime.h>
#include <cstdint>

#define B_ 8
#define T_ 4096
#define D_ 256
#define H_ 256
#define G_ 768              // 3H
#define M_ (B_ * T_)        // 32768
#define CANARY 0x7FC00001u  // NaN pattern; h is always finite

// Scratch (static device allocations only)
// xg layout (scan-permuted): [d][b][t][rank(4)][w(8)][gate(3)][j(8)]
__device__ float g_xg[(size_t)2 * B_ * T_ * G_];
__device__ float g_outc[(size_t)B_ * T_ * 2 * H_];     // [b][t][512]  (fwd | bwd)

typedef unsigned long long ull;

__device__ __forceinline__ uint32_t s2u(const void* p) {
    uint32_t a;
    asm("{ .reg .u64 t; cvta.to.shared.u64 t, %1; cvt.u32.u64 %0, t; }"
        : "=r"(a) : "l"(p));
    return a;
}
__device__ __forceinline__ ull ffma2(ull a, ull b, ull c) {
    ull d;
    asm("fma.rn.f32x2 %0, %1, %2, %3;" : "=l"(d) : "l"(a), "l"(b), "l"(c));
    return d;
}
__device__ __forceinline__ ull fadd2(ull a, ull b) {
    ull d;
    asm("add.rn.f32x2 %0, %1, %2;" : "=l"(d) : "l"(a), "l"(b));
    return d;
}
__device__ __forceinline__ ull pack2(float lo, float hi) {
    ull r;
    asm("mov.b64 %0, {%1, %2};" : "=l"(r)
        : "r"(__float_as_uint(lo)), "r"(__float_as_uint(hi)));
    return r;
}
__device__ __forceinline__ ull dup2(float v) {
    ull r;
    asm("mov.b64 %0, {%1, %1};" : "=l"(r) : "r"(__float_as_uint(v)));
    return r;
}
__device__ __forceinline__ void unpack2(ull a, float& lo, float& hi) {
    uint32_t l, h;
    asm("mov.b64 {%0, %1}, %2;" : "=r"(l), "=r"(h) : "l"(a));
    lo = __uint_as_float(l); hi = __uint_as_float(h);
}
__device__ __forceinline__ float sum2(ull a) {
    float lo, hi; unpack2(a, lo, hi); return lo + hi;
}
__device__ __forceinline__ float fast_sigmoid(float x) {
    float e, r;
    asm("ex2.approx.f32 %0, %1;" : "=f"(e) : "f"(-1.4426950408889634f * x));
    asm("rcp.approx.f32 %0, %1;" : "=f"(r) : "f"(1.0f + e));
    return r;
}
__device__ __forceinline__ float fast_tanh(float x) {
    float e, r;
    asm("ex2.approx.f32 %0, %1;" : "=f"(e) : "f"(-2.8853900817779268f * x));
    asm("rcp.approx.f32 %0, %1;" : "=f"(r) : "f"(1.0f + e));
    return fmaf(2.0f, r, -1.0f);
}
__device__ __forceinline__ float fast_exp(float x) {
    float e;
    asm("ex2.approx.f32 %0, %1;" : "=f"(e) : "f"(1.4426950408889634f * x));
    return e;
}

// ---------------------------------------------------------------------------
// Kernel A: xg[d] = X @ Wi_d + bi_d   X:[32768,256], Wi:[256,768]
// FFMA2, non-duplicated B in smem, DOUBLE-BUFFERED tiles (1 sync per K-tile).
// Output permuted to scan layout: col n -> rank*192 + w*24 + gate*8 + j.
// ---------------------------------------------------------------------------
__global__ void __launch_bounds__(256) k_xgemm(
    const float* __restrict__ X,
    const float* __restrict__ Wi_f, const float* __restrict__ bi_f,
    const float* __restrict__ Wi_b, const float* __restrict__ bi_b)
{
    const int d = blockIdx.z;
    const float* W  = d ? Wi_b : Wi_f;
    const float* bi = d ? bi_b : bi_f;
    float* out = g_xg + (size_t)d * M_ * G_;

    const int m0 = blockIdx.y * 128;
    const int n0 = blockIdx.x * 64;

    __shared__ __align__(16) float As[2][16][136];   // [stage][k][m]
    __shared__ __align__(16) float Bs[2][16][68];    // [stage][k][n]

    const int tid = threadIdx.x;
    const int ti = tid >> 4;        // 8 rows (4 row-pairs)
    const int tj = tid & 15;        // 4 cols
    const int ar = tid >> 4, ac = tid & 15;   // A-load coords (r stride 16)
    const int br = tid >> 6, bc = tid & 63;   // B-load coords (r stride 4)

    ull acc2[4][4];
#pragma unroll
    for (int i = 0; i < 4; ++i)
#pragma unroll
        for (int j = 0; j < 4; ++j) acc2[i][j] = 0ull;

    // prologue: stage 0
#pragma unroll
    for (int p = 0; p < 8; ++p)
        As[0][ac][ar + p * 16] = X[(size_t)(m0 + ar + p * 16) * D_ + ac];
#pragma unroll
    for (int p = 0; p < 4; ++p)
        Bs[0][br + p * 4][bc] = W[(size_t)(br + p * 4) * G_ + n0 + bc];
    __syncthreads();

    int buf = 0;
    for (int k0 = 0; k0 < D_; k0 += 16) {
        // prefetch next tile into registers
        float xa[8], xb[4];
        if (k0 + 16 < D_) {
#pragma unroll
            for (int p = 0; p < 8; ++p)
                xa[p] = X[(size_t)(m0 + ar + p * 16) * D_ + k0 + 16 + ac];
#pragma unroll
            for (int p = 0; p < 4; ++p)
                xb[p] = W[(size_t)(k0 + 16 + br + p * 4) * G_ + n0 + bc];
        }

        // compute on current buffer
#pragma unroll
        for (int kk = 0; kk < 16; ++kk) {
            ull ap[4];
            const ull* arow = (const ull*)&As[buf][kk][ti * 8];
            ap[0] = arow[0]; ap[1] = arow[1]; ap[2] = arow[2]; ap[3] = arow[3];
            float4 bq = *(const float4*)&Bs[buf][kk][tj * 4];
            ull bd[4];
            bd[0] = dup2(bq.x); bd[1] = dup2(bq.y);
            bd[2] = dup2(bq.z); bd[3] = dup2(bq.w);
#pragma unroll
            for (int i = 0; i < 4; ++i)
#pragma unroll
                for (int j = 0; j < 4; ++j)
                    acc2[i][j] = ffma2(ap[i], bd[j], acc2[i][j]);
        }

        // store prefetched tile to the other buffer
        if (k0 + 16 < D_) {
#pragma unroll
            for (int p = 0; p < 8; ++p) As[buf ^ 1][ac][ar + p * 16] = xa[p];
#pragma unroll
            for (int p = 0; p < 4; ++p) Bs[buf ^ 1][br + p * 4][bc] = xb[p];
            __syncthreads();
            buf ^= 1;
        }
    }

    // permuted store: n -> rank*192 + w*24 + gate*8 + j
    const int n = n0 + tj * 4;
    const int g = n >> 8, u = n & 255;
    const int pos = (u >> 6) * 192 + ((u >> 3) & 7) * 24 + g * 8 + (u & 7);
    float4 bb = *(const float4*)&bi[n];
#pragma unroll
    for (int i = 0; i < 4; ++i) {
        float4 o0, o1;
        unpack2(acc2[i][0], o0.x, o1.x);
        unpack2(acc2[i][1], o0.y, o1.y);
        unpack2(acc2[i][2], o0.z, o1.z);
        unpack2(acc2[i][3], o0.w, o1.w);
        o0.x += bb.x; o0.y += bb.y; o0.z += bb.z; o0.w += bb.w;
        o1.x += bb.x; o1.y += bb.y; o1.z += bb.z; o1.w += bb.w;
        *(float4*)&out[(size_t)(m0 + ti * 8 + i * 2)     * G_ + pos] = o0;
        *(float4*)&out[(size_t)(m0 + ti * 8 + i * 2 + 1) * G_ + pos] = o1;
    }
}

// ---------------------------------------------------------------------------
// Kernel B: 4-CTA clustered bidirectional GRU scan. (Round-10/12 version —
// best measured; FROZEN.) Warp-autonomous 4-buffer canary ring, no
// __syncthreads in the loop, per-warp coalesced 16B sends to all 4 CTAs.
// ---------------------------------------------------------------------------
__global__ void __launch_bounds__(256, 1) __cluster_dims__(4, 1, 1)
k_scan(const float* __restrict__ Wh_f, const float* __restrict__ bhn_f,
       const float* __restrict__ Wh_b, const float* __restrict__ bhn_b)
{
    __shared__ __align__(16) float hbuf[4][272];   // 4 blocks x (64 data + 4 pad)
    __shared__ __align__(16) float hist[16][64];   // output staging

    const uint32_t hbuf_a = s2u(hbuf);

    const int rank = blockIdx.x & 3;
    const int cid  = blockIdx.x >> 2;
    const int d    = cid >> 3;
    const int b    = cid & 7;

    const float* Wh  = d ? Wh_b  : Wh_f;
    const float* bhn = d ? bhn_b : bhn_f;

    const int tid  = threadIdx.x;
    const int w    = tid >> 5;
    const int lane = tid & 31;
    const int kq   = lane >> 3;                    // K-chunk of 64 (0..3)
    const int j    = lane & 7;                     // unit within warp (0..7)
    const int unit = rank * 64 + w * 8 + j;

    // ---- W slice fully in registers: 96 b64 per lane ----
    ull Wr2[32], Wz2[32], Wn2[32];
#pragma unroll
    for (int kk = 0; kk < 32; ++kk) {
        size_t r0 = (size_t)(kq * 64 + kk * 2) * G_;
        size_t r1 = r0 + G_;
        Wr2[kk] = pack2(__ldg(Wh + r0 + unit),       __ldg(Wh + r1 + unit));
        Wz2[kk] = pack2(__ldg(Wh + r0 + 256 + unit), __ldg(Wh + r1 + 256 + unit));
        Wn2[kk] = pack2(__ldg(Wh + r0 + 512 + unit), __ldg(Wh + r1 + 512 + unit));
    }

    // init: buf0 = h0 = 0, buf1..3 = canary
    for (int i = tid; i < 272; i += 256) {
        hbuf[0][i] = 0.f;
        ((unsigned*)hbuf[1])[i] = CANARY;
        ((unsigned*)hbuf[2])[i] = CANARY;
        ((unsigned*)hbuf[3])[i] = CANARY;
    }
    __syncthreads();
    asm volatile("barrier.cluster.arrive.aligned;" ::: "memory");
    asm volatile("barrier.cluster.wait.aligned;"   ::: "memory");

    // send address (lanes 0..7): peer = (rank + (lane>>1)) & 3 (incl. self),
    // half = lane&1. Warp w's 8 units live at words rank*68 + w*8 (+half*4).
    uint32_t sdata = 0;
    if (lane < 8) {
        uint32_t peer = (uint32_t)((rank + (lane >> 1)) & 3);
        uint32_t rhb;
        asm("mapa.shared::cluster.u32 %0, %1, %2;" : "=r"(rhb) : "r"(hbuf_a), "r"(peer));
        sdata = rhb + (uint32_t)(rank * 272 + w * 32 + (lane & 1) * 16);
    }

    // poll address: lane waits on producer warp j of CTA kq (8 words, 2 v4)
    const uint32_t pa = hbuf_a + (uint32_t)(kq * 272 + j * 32);
    // re-canary partition: warp w owns block (w>>1), half (w&1), word lane
    const uint32_t ca = hbuf_a + (uint32_t)((w >> 1) * 272 + (w & 1) * 128 + lane * 4);

    const float bhn_u = bhn[unit];
    const float* xgp = g_xg + ((size_t)(d * B_ + b)) * T_ * G_ + rank * 192 + w * 24;

    // 3-deep gi prefetch ring (lanes 0..23: gate = lane>>3, j = lane&7)
    float gv0 = 0.f, gv1 = 0.f, gv2 = 0.f;
    if (lane < 24) {
        gv0 = __ldg(xgp + (size_t)(d ? T_ - 1 : 0) * G_ + lane);
        gv1 = __ldg(xgp + (size_t)(d ? T_ - 2 : 1) * G_ + lane);
        gv2 = __ldg(xgp + (size_t)(d ? T_ - 3 : 2) * G_ + lane);
    }

    float hprev = 0.f;

    for (int s = 0; s < T_; ++s) {
        const int q = s & 3;

        // ---- 1. poll: this lane's producer-warp words present ----
        {
            const uint32_t a = pa + (uint32_t)q * 1088;
            for (;;) {
                uint32_t x0, x1, x2, x3, y0, y1, y2, y3;
                asm volatile("ld.volatile.shared.v4.u32 {%0,%1,%2,%3}, [%4];"
                             : "=r"(x0), "=r"(x1), "=r"(x2), "=r"(x3) : "r"(a));
                asm volatile("ld.volatile.shared.v4.u32 {%0,%1,%2,%3}, [%4];"
                             : "=r"(y0), "=r"(y1), "=r"(y2), "=r"(y3) : "r"(a + 16));
                bool bad = (x0 == CANARY) | (x1 == CANARY) | (x2 == CANARY) |
                           (x3 == CANARY) | (y0 == CANARY) | (y1 == CANARY) |
                           (y2 == CANARY) | (y3 == CANARY);
                if (!__any_sync(0xFFFFFFFFu, bad)) break;
            }
        }

        // ---- 2. re-canary buf (q+2)&3 (read-complete: all warps >= s-1) ----
        {
            const uint32_t a = ca + (uint32_t)((q + 2) & 3) * 1088;
            asm volatile("st.shared.u32 [%0], %1;" :: "r"(a), "r"(CANARY) : "memory");
        }

        // ---- 3. dots: this lane's 64-K chunk (block kq) ----
        const float* hp = &hbuf[q][kq * 68];
        ull ar0 = 0, ar1 = 0, az0 = 0, az1 = 0, an0 = 0, an1 = 0;
#pragma unroll
        for (int qq = 0; qq < 16; ++qq) {
            ulonglong2 hv2 = *(const ulonglong2*)(hp + qq * 4);
            ar0 = ffma2(Wr2[qq * 2],     hv2.x, ar0);
            ar1 = ffma2(Wr2[qq * 2 + 1], hv2.y, ar1);
            az0 = ffma2(Wz2[qq * 2],     hv2.x, az0);
            az1 = ffma2(Wz2[qq * 2 + 1], hv2.y, az1);
            an0 = ffma2(Wn2[qq * 2],     hv2.x, an0);
            an1 = ffma2(Wn2[qq * 2 + 1], hv2.y, an1);
        }
        float sr = sum2(fadd2(ar0, ar1));
        float sz = sum2(fadd2(az0, az1));
        float sn = sum2(fadd2(an0, an1));
#pragma unroll
        for (int m = 8; m <= 16; m <<= 1) {        // reduce over kq
            sr += __shfl_xor_sync(0xFFFFFFFFu, sr, m);
            sz += __shfl_xor_sync(0xFFFFFFFFu, sz, m);
            sn += __shfl_xor_sync(0xFFFFFFFFu, sn, m);
        }

        float gr = __shfl_sync(0xFFFFFFFFu, gv0, j);
        float gz = __shfl_sync(0xFFFFFFFFu, gv0, 8 + j);
        float gn = __shfl_sync(0xFFFFFFFFu, gv0, 16 + j);

        {
            float r = fast_sigmoid(gr + sr);
            float z = fast_sigmoid(gz + sz);
            float n = fast_tanh(fmaf(r, sn + bhn_u, gn));
            hprev = fmaf(z, hprev - n, n);          // h_new, all lanes
        }

        // ---- 4. send: warp's 8 units to all 4 CTAs (8 lanes x 1 v4) ----
        if (s + 1 < T_) {
            const uint32_t qoff = (uint32_t)((s + 1) & 3) * 1088;
            const int base = (lane & 1) * 4;
            float4 v;
            v.x = __shfl_sync(0xFFFFFFFFu, hprev, base + 0);
            v.y = __shfl_sync(0xFFFFFFFFu, hprev, base + 1);
            v.z = __shfl_sync(0xFFFFFFFFu, hprev, base + 2);
            v.w = __shfl_sync(0xFFFFFFFFu, hprev, base + 3);
            if (lane < 8) {
                asm volatile("st.shared::cluster.v4.b32 [%0], {%1, %2, %3, %4};"
                             :: "r"(sdata + qoff),
                                "r"(__float_as_uint(v.x)), "r"(__float_as_uint(v.y)),
                                "r"(__float_as_uint(v.z)), "r"(__float_as_uint(v.w))
                             : "memory");
            }
            // advance gi ring (prefetch s+3)
            gv0 = gv1; gv1 = gv2;
            if (lane < 24 && s + 3 < T_) {
                const int tn = d ? (T_ - 4 - s) : (s + 3);
                gv2 = __ldg(xgp + (size_t)tn * G_ + lane);
            }
        }

        // ---- 5. stage output ----
        if (lane < 8) hist[s & 15][w * 8 + lane] = hprev;

        // ---- 6. skew-safe flush: rows [s-14, s-7] (all provably written) ----
        if ((s & 7) == 7) {
            const int rr = s - 14 + w;
            if (rr >= 0) {
                const int tw = d ? (T_ - 1 - rr) : rr;
                *(float2*)&g_outc[((size_t)b * T_ + tw) * 512 + d * 256 +
                                  rank * 64 + lane * 2] =
                    *(const float2*)&hist[rr & 15][lane * 2];
            }
        }
    }

    // tail: rows 4089..4095 (warps 1..7), after all warps finish
    __syncthreads();
    if (w >= 1) {
        const int rr = 4088 + w;
        const int tw = d ? (T_ - 1 - rr) : rr;
        *(float2*)&g_outc[((size_t)b * T_ + tw) * 512 + d * 256 +
                          rank * 64 + lane * 2] =
            *(const float2*)&hist[rr & 15][lane * 2];
    }

    // no CTA may exit while peers can still write its smem
    asm volatile("barrier.cluster.arrive.aligned;" ::: "memory");
    asm volatile("barrier.cluster.wait.aligned;"   ::: "memory");
}

// ---------------------------------------------------------------------------
// Kernel C: heads. out_combined [32768,512] @ (Wm|Wv) [512,256] + bias.
// FFMA2, non-duplicated B, DOUBLE-BUFFERED tiles, fast exp epilogue.
// ---------------------------------------------------------------------------
__global__ void __launch_bounds__(256) k_heads(
    const float* __restrict__ Wm, const float* __restrict__ bm,
    const float* __restrict__ Wv, const float* __restrict__ bv,
    float* __restrict__ out)
{
    const int n0 = blockIdx.x * 64;
    const int m0 = blockIdx.y * 128;
    const bool isV = (n0 >= 256);
    const float* W  = isV ? Wv : Wm;
    const float* bb = isV ? bv : bm;
    const int nw = n0 & 255;

    __shared__ __align__(16) float As[2][16][136];
    __shared__ __align__(16) float Bs[2][16][68];

    const int tid = threadIdx.x;
    const int ti = tid >> 4, tj = tid & 15;
    const int ar = tid >> 4, ac = tid & 15;
    const int br = tid >> 6, bc = tid & 63;

    ull acc2[4][4];
#pragma unroll
    for (int i = 0; i < 4; ++i)
#pragma unroll
        for (int j = 0; j < 4; ++j) acc2[i][j] = 0ull;

    // prologue: stage 0
#pragma unroll
    for (int p = 0; p < 8; ++p)
        As[0][ac][ar + p * 16] = g_outc[(size_t)(m0 + ar + p * 16) * 512 + ac];
#pragma unroll
    for (int p = 0; p < 4; ++p)
        Bs[0][br + p * 4][bc] = W[(size_t)(br + p * 4) * 256 + nw + bc];
    __syncthreads();

    int buf = 0;
    for (int k0 = 0; k0 < 512; k0 += 16) {
        float xa[8], xb[4];
        if (k0 + 16 < 512) {
#pragma unroll
            for (int p = 0; p < 8; ++p)
                xa[p] = g_outc[(size_t)(m0 + ar + p * 16) * 512 + k0 + 16 + ac];
#pragma unroll
            for (int p = 0; p < 4; ++p)
                xb[p] = W[(size_t)(k0 + 16 + br + p * 4) * 256 + nw + bc];
        }

#pragma unroll
        for (int kk = 0; kk < 16; ++kk) {
            ull ap[4];
            const ull* arow = (const ull*)&As[buf][kk][ti * 8];
            ap[0] = arow[0]; ap[1] = arow[1]; ap[2] = arow[2]; ap[3] = arow[3];
            float4 bq = *(const float4*)&Bs[buf][kk][tj * 4];
            ull bd[4];
            bd[0] = dup2(bq.x); bd[1] = dup2(bq.y);
            bd[2] = dup2(bq.z); bd[3] = dup2(bq.w);
#pragma unroll
            for (int i = 0; i < 4; ++i)
#pragma unroll
                for (int jj = 0; jj < 4; ++jj)
                    acc2[i][jj] = ffma2(ap[i], bd[jj], acc2[i][jj]);
        }

        if (k0 + 16 < 512) {
#pragma unroll
            for (int p = 0; p < 8; ++p) As[buf ^ 1][ac][ar + p * 16] = xa[p];
#pragma unroll
            for (int p = 0; p < 4; ++p) Bs[buf ^ 1][br + p * 4][bc] = xb[p];
            __syncthreads();
            buf ^= 1;
        }
    }

    const size_t hofs = (size_t)M_ * H_;
    float4 bb4 = *(const float4*)&bb[nw + tj * 4];
#pragma unroll
    for (int i = 0; i < 4; ++i) {
        float4 o0, o1;
        unpack2(acc2[i][0], o0.x, o1.x);
        unpack2(acc2[i][1], o0.y, o1.y);
        unpack2(acc2[i][2], o0.z, o1.z);
        unpack2(acc2[i][3], o0.w, o1.w);
        o0.x += bb4.x; o0.y += bb4.y; o0.z += bb4.z; o0.w += bb4.w;
        o1.x += bb4.x; o1.y += bb4.y; o1.z += bb4.z; o1.w += bb4.w;
        int r0 = m0 + ti * 8 + i * 2, r1 = r0 + 1;
        if (isV) {
            o0.x = fast_exp(o0.x); o0.y = fast_exp(o0.y);
            o0.z = fast_exp(o0.z); o0.w = fast_exp(o0.w);
            o1.x = fast_exp(o1.x); o1.y = fast_exp(o1.y);
            o1.z = fast_exp(o1.z); o1.w = fast_exp(o1.w);
            *(float4*)&out[(size_t)r0 * 256 + nw + tj * 4] = o0;
            *(float4*)&out[(size_t)r1 * 256 + nw + tj * 4] = o1;
        } else {
            *(float4*)&out[hofs + (size_t)r0 * 256 + nw + tj * 4] = o0;
            *(float4*)&out[hofs + (size_t)r1 * 256 + nw + tj * 4] = o1;
        }
    }
}

// ---------------------------------------------------------------------------
extern "C" void kernel_launch(void* const* d_in, const int* in_sizes, int n_in,
                              void* d_out, int out_size)
{
    const float* inputs = (const float*)d_in[0];
    const float* Wi_f   = (const float*)d_in[1];
    const float* bi_f   = (const float*)d_in[2];
    const float* Wh_f   = (const float*)d_in[3];
    const float* bhn_f  = (const float*)d_in[4];
    const float* Wi_b   = (const float*)d_in[5];
    const float* bi_b   = (const float*)d_in[6];
    const float* Wh_b   = (const float*)d_in[7];
    const float* bhn_b  = (const float*)d_in[8];
    const float* Wm     = (const float*)d_in[9];
    const float* bm     = (const float*)d_in[10];
    const float* Wv     = (const float*)d_in[11];
    const float* bv     = (const float*)d_in[12];
    float* out = (float*)d_out;

    (void)in_sizes; (void)n_in; (void)out_size;

    k_xgemm<<<dim3(12, 256, 2), 256>>>(inputs, Wi_f, bi_f, Wi_b, bi_b);
    k_scan<<<64, 256>>>(Wh_f, bhn_f, Wh_b, bhn_b);
    k_heads<<<dim3(8, 256), 256>>>(Wm, bm, Wv, bv, out);
}

// round 14
// speedup vs baseline: 1.5631x; 1.1339x over previous
#include <cuda_runtime.h>
#include <cstdint>

#define B_ 8
#define T_ 4096
#define D_ 256
#define H_ 256
#define G_ 768              // 3H
#define M_ (B_ * T_)        // 32768
#define CANARY 0x7FC00001u  // NaN pattern; h is always finite
#define NTILES 6144         // 2 dirs x 256 m-tiles x 12 n-tiles

// Scratch (static device allocations only)
// xg layout (scan-permuted): [d][b][t][rank(4)][w(8)][gate(3)][j(8)]
__device__ float g_xg[(size_t)2 * B_ * T_ * G_];
__device__ float g_outc[(size_t)B_ * T_ * 2 * H_];     // [b][t][512]  (fwd | bwd)
__device__ unsigned g_cnt[2 * 8 * 32];                 // [d][b][tc] tile counters
__device__ unsigned g_tilectr;                         // worker tile queue

typedef unsigned long long ull;

__device__ __forceinline__ uint32_t s2u(const void* p) {
    uint32_t a;
    asm("{ .reg .u64 t; cvta.to.shared.u64 t, %1; cvt.u32.u64 %0, t; }"
        : "=r"(a) : "l"(p));
    return a;
}
__device__ __forceinline__ ull ffma2(ull a, ull b, ull c) {
    ull d;
    asm("fma.rn.f32x2 %0, %1, %2, %3;" : "=l"(d) : "l"(a), "l"(b), "l"(c));
    return d;
}
__device__ __forceinline__ ull fadd2(ull a, ull b) {
    ull d;
    asm("add.rn.f32x2 %0, %1, %2;" : "=l"(d) : "l"(a), "l"(b));
    return d;
}
__device__ __forceinline__ ull pack2(float lo, float hi) {
    ull r;
    asm("mov.b64 %0, {%1, %2};" : "=l"(r)
        : "r"(__float_as_uint(lo)), "r"(__float_as_uint(hi)));
    return r;
}
__device__ __forceinline__ ull dup2(float v) {
    ull r;
    asm("mov.b64 %0, {%1, %1};" : "=l"(r) : "r"(__float_as_uint(v)));
    return r;
}
__device__ __forceinline__ void unpack2(ull a, float& lo, float& hi) {
    uint32_t l, h;
    asm("mov.b64 {%0, %1}, %2;" : "=r"(l), "=r"(h) : "l"(a));
    lo = __uint_as_float(l); hi = __uint_as_float(h);
}
__device__ __forceinline__ float sum2(ull a) {
    float lo, hi; unpack2(a, lo, hi); return lo + hi;
}
__device__ __forceinline__ float fast_sigmoid(float x) {
    float e, r;
    asm("ex2.approx.f32 %0, %1;" : "=f"(e) : "f"(-1.4426950408889634f * x));
    asm("rcp.approx.f32 %0, %1;" : "=f"(r) : "f"(1.0f + e));
    return r;
}
__device__ __forceinline__ float fast_tanh(float x) {
    float e, r;
    asm("ex2.approx.f32 %0, %1;" : "=f"(e) : "f"(-2.8853900817779268f * x));
    asm("rcp.approx.f32 %0, %1;" : "=f"(r) : "f"(1.0f + e));
    return fmaf(2.0f, r, -1.0f);
}
__device__ __forceinline__ float fast_exp(float x) {
    float e;
    asm("ex2.approx.f32 %0, %1;" : "=f"(e) : "f"(1.4426950408889634f * x));
    return e;
}
__device__ __forceinline__ void wait_cnt12(const unsigned* p) {
    unsigned v;
    do {
        asm volatile("ld.acquire.gpu.global.u32 %0, [%1];" : "=r"(v) : "l"(p));
    } while (v < 12u);
}

// ---------------------------------------------------------------------------
// k_init: reset counters + work queue (stream-ordered before k_mega).
// ---------------------------------------------------------------------------
__global__ void k_init() {
    if (threadIdx.x < 512) g_cnt[threadIdx.x] = 0u;
    if (threadIdx.x == 0)  g_tilectr = 0u;
}

// ---------------------------------------------------------------------------
// One 128x64 xgemm tile (FFMA2, double-buffered), permuted store to g_xg.
// ---------------------------------------------------------------------------
__device__ __forceinline__ void gemm_tile(
    const float* __restrict__ X, const float* __restrict__ W,
    const float* __restrict__ bi, float* __restrict__ out,
    int m0, int n0,
    float (&As)[2][16][136], float (&Bs)[2][16][68])
{
    const int tid = threadIdx.x;
    const int ti = tid >> 4;
    const int tj = tid & 15;
    const int ar = tid >> 4, ac = tid & 15;
    const int br = tid >> 6, bc = tid & 63;

    ull acc2[4][4];
#pragma unroll
    for (int i = 0; i < 4; ++i)
#pragma unroll
        for (int j = 0; j < 4; ++j) acc2[i][j] = 0ull;

    // prologue: stage 0
#pragma unroll
    for (int p = 0; p < 8; ++p)
        As[0][ac][ar + p * 16] = X[(size_t)(m0 + ar + p * 16) * D_ + ac];
#pragma unroll
    for (int p = 0; p < 4; ++p)
        Bs[0][br + p * 4][bc] = W[(size_t)(br + p * 4) * G_ + n0 + bc];
    __syncthreads();

    int buf = 0;
    for (int k0 = 0; k0 < D_; k0 += 16) {
        float xa[8], xb[4];
        if (k0 + 16 < D_) {
#pragma unroll
            for (int p = 0; p < 8; ++p)
                xa[p] = X[(size_t)(m0 + ar + p * 16) * D_ + k0 + 16 + ac];
#pragma unroll
            for (int p = 0; p < 4; ++p)
                xb[p] = W[(size_t)(k0 + 16 + br + p * 4) * G_ + n0 + bc];
        }
#pragma unroll
        for (int kk = 0; kk < 16; ++kk) {
            ull ap[4];
            const ull* arow = (const ull*)&As[buf][kk][ti * 8];
            ap[0] = arow[0]; ap[1] = arow[1]; ap[2] = arow[2]; ap[3] = arow[3];
            float4 bq = *(const float4*)&Bs[buf][kk][tj * 4];
            ull bd[4];
            bd[0] = dup2(bq.x); bd[1] = dup2(bq.y);
            bd[2] = dup2(bq.z); bd[3] = dup2(bq.w);
#pragma unroll
            for (int i = 0; i < 4; ++i)
#pragma unroll
                for (int j = 0; j < 4; ++j)
                    acc2[i][j] = ffma2(ap[i], bd[j], acc2[i][j]);
        }
        if (k0 + 16 < D_) {
#pragma unroll
            for (int p = 0; p < 8; ++p) As[buf ^ 1][ac][ar + p * 16] = xa[p];
#pragma unroll
            for (int p = 0; p < 4; ++p) Bs[buf ^ 1][br + p * 4][bc] = xb[p];
            __syncthreads();
            buf ^= 1;
        }
    }

    // permuted store: n -> rank*192 + w*24 + gate*8 + j
    const int n = n0 + tj * 4;
    const int g = n >> 8, u = n & 255;
    const int pos = (u >> 6) * 192 + ((u >> 3) & 7) * 24 + g * 8 + (u & 7);
    float4 bb = *(const float4*)&bi[n];
#pragma unroll
    for (int i = 0; i < 4; ++i) {
        float4 o0, o1;
        unpack2(acc2[i][0], o0.x, o1.x);
        unpack2(acc2[i][1], o0.y, o1.y);
        unpack2(acc2[i][2], o0.z, o1.z);
        unpack2(acc2[i][3], o0.w, o1.w);
        o0.x += bb.x; o0.y += bb.y; o0.z += bb.z; o0.w += bb.w;
        o1.x += bb.x; o1.y += bb.y; o1.z += bb.z; o1.w += bb.w;
        *(float4*)&out[(size_t)(m0 + ti * 8 + i * 2)     * G_ + pos] = o0;
        *(float4*)&out[(size_t)(m0 + ti * 8 + i * 2 + 1) * G_ + pos] = o1;
    }
}

// ---------------------------------------------------------------------------
// k_mega: 37 clusters x 4 CTAs.
//   blockIdx 0..63  : GRU scan (frozen R10/12 protocol) + gi readiness polls
//   blockIdx 64..147: xgemm workers pulling tiles from a priority work queue
// Workers publish per-(d,b,tc) counters (release); scan acquires them once
// per 128 steps. Workers never wait on the scan -> no deadlock possible.
// ---------------------------------------------------------------------------
__global__ void __launch_bounds__(256, 1) __cluster_dims__(4, 1, 1)
k_mega(const float* __restrict__ X,
       const float* __restrict__ Wi_f, const float* __restrict__ bi_f,
       const float* __restrict__ Wi_b, const float* __restrict__ bi_b,
       const float* __restrict__ Wh_f, const float* __restrict__ bhn_f,
       const float* __restrict__ Wh_b, const float* __restrict__ bhn_b)
{
    __shared__ __align__(16) float As[2][16][136];   // worker tiles
    __shared__ __align__(16) float Bs[2][16][68];
    __shared__ __align__(16) float hbuf[4][272];     // scan ring
    __shared__ __align__(16) float hist[16][64];     // scan output staging
    __shared__ int s_idx;

    const int tid = threadIdx.x;

    if (blockIdx.x >= 64) {
        // ================= WORKER PATH =================
        for (;;) {
            if (tid == 0) s_idx = (int)atomicAdd(&g_tilectr, 1u);
            __syncthreads();
            const int idx = s_idx;
            if (idx >= NTILES) break;

            // priority order: k=2i -> (d=0, tc=i); k=2i+1 -> (d=1, tc=31-i)
            const int k  = idx / 96;
            const int r  = idx - k * 96;
            const int bb = r / 12;
            const int bx = r - bb * 12;
            const int dd = k & 1;
            const int ii = k >> 1;
            const int tc = dd ? (31 - ii) : ii;
            const int m0 = (bb * 32 + tc) * 128;
            const int n0 = bx * 64;

            gemm_tile(X, dd ? Wi_b : Wi_f, dd ? bi_b : bi_f,
                      g_xg + (size_t)dd * M_ * G_, m0, n0, As, Bs);

            __threadfence();
            __syncthreads();
            if (tid == 0) {
                const unsigned* p = &g_cnt[(dd * 8 + bb) * 32 + tc];
                asm volatile("red.release.gpu.global.add.u32 [%0], %1;"
                             :: "l"(p), "r"(1u) : "memory");
            }
        }
        return;
    }

    // ================= SCAN PATH (frozen protocol) =================
    const uint32_t hbuf_a = s2u(hbuf);

    const int rank = blockIdx.x & 3;
    const int cid  = blockIdx.x >> 2;
    const int d    = cid >> 3;
    const int b    = cid & 7;

    const float* Wh  = d ? Wh_b  : Wh_f;
    const float* bhn = d ? bhn_b : bhn_f;

    const int w    = tid >> 5;
    const int lane = tid & 31;
    const int kq   = lane >> 3;
    const int j    = lane & 7;
    const int unit = rank * 64 + w * 8 + j;
    const unsigned* cbase = &g_cnt[(d * 8 + b) * 32];

    // W slice fully in registers: 96 b64 per lane
    ull Wr2[32], Wz2[32], Wn2[32];
#pragma unroll
    for (int kk = 0; kk < 32; ++kk) {
        size_t r0 = (size_t)(kq * 64 + kk * 2) * G_;
        size_t r1 = r0 + G_;
        Wr2[kk] = pack2(__ldg(Wh + r0 + unit),       __ldg(Wh + r1 + unit));
        Wz2[kk] = pack2(__ldg(Wh + r0 + 256 + unit), __ldg(Wh + r1 + 256 + unit));
        Wn2[kk] = pack2(__ldg(Wh + r0 + 512 + unit), __ldg(Wh + r1 + 512 + unit));
    }

    for (int i = tid; i < 272; i += 256) {
        hbuf[0][i] = 0.f;
        ((unsigned*)hbuf[1])[i] = CANARY;
        ((unsigned*)hbuf[2])[i] = CANARY;
        ((unsigned*)hbuf[3])[i] = CANARY;
    }
    __syncthreads();
    asm volatile("barrier.cluster.arrive.aligned;" ::: "memory");
    asm volatile("barrier.cluster.wait.aligned;"   ::: "memory");

    uint32_t sdata = 0;
    if (lane < 8) {
        uint32_t peer = (uint32_t)((rank + (lane >> 1)) & 3);
        uint32_t rhb;
        asm("mapa.shared::cluster.u32 %0, %1, %2;" : "=r"(rhb) : "r"(hbuf_a), "r"(peer));
        sdata = rhb + (uint32_t)(rank * 272 + w * 32 + (lane & 1) * 16);
    }
    const uint32_t pa = hbuf_a + (uint32_t)(kq * 272 + j * 32);
    const uint32_t ca = hbuf_a + (uint32_t)((w >> 1) * 272 + (w & 1) * 128 + lane * 4);

    const float bhn_u = bhn[unit];
    const float* xgp = g_xg + ((size_t)(d * B_ + b)) * T_ * G_ + rank * 192 + w * 24;

    // readiness for the first gi block (tc pair for a=0)
    wait_cnt12(cbase + (d ? 31 : 0));
    wait_cnt12(cbase + (d ? 30 : 1));

    // 3-deep gi prefetch ring
    float gv0 = 0.f, gv1 = 0.f, gv2 = 0.f;
    if (lane < 24) {
        gv0 = __ldg(xgp + (size_t)(d ? T_ - 1 : 0) * G_ + lane);
        gv1 = __ldg(xgp + (size_t)(d ? T_ - 2 : 1) * G_ + lane);
        gv2 = __ldg(xgp + (size_t)(d ? T_ - 3 : 2) * G_ + lane);
    }

    float hprev = 0.f;

    for (int s = 0; s < T_; ++s) {
        const int q = s & 3;

        // gi readiness poll: once per 128 steps, covers prefetch lookahead
        if ((s & 127) == 0 && s) {
            const int a = s >> 7;
            const int c0 = d ? (31 - a) : a;
            const int c1n = (a < 31) ? (a + 1) : 31;
            const int c1 = d ? (31 - c1n) : c1n;
            wait_cnt12(cbase + c0);
            wait_cnt12(cbase + c1);
        }

        // 1. poll canary: this lane's producer-warp words present
        {
            const uint32_t a = pa + (uint32_t)q * 1088;
            for (;;) {
                uint32_t x0, x1, x2, x3, y0, y1, y2, y3;
                asm volatile("ld.volatile.shared.v4.u32 {%0,%1,%2,%3}, [%4];"
                             : "=r"(x0), "=r"(x1), "=r"(x2), "=r"(x3) : "r"(a));
                asm volatile("ld.volatile.shared.v4.u32 {%0,%1,%2,%3}, [%4];"
                             : "=r"(y0), "=r"(y1), "=r"(y2), "=r"(y3) : "r"(a + 16));
                bool bad = (x0 == CANARY) | (x1 == CANARY) | (x2 == CANARY) |
                           (x3 == CANARY) | (y0 == CANARY) | (y1 == CANARY) |
                           (y2 == CANARY) | (y3 == CANARY);
                if (!__any_sync(0xFFFFFFFFu, bad)) break;
            }
        }

        // 2. re-canary buf (q+2)&3
        {
            const uint32_t a = ca + (uint32_t)((q + 2) & 3) * 1088;
            asm volatile("st.shared.u32 [%0], %1;" :: "r"(a), "r"(CANARY) : "memory");
        }

        // 3. dots: this lane's 64-K chunk (block kq)
        const float* hp = &hbuf[q][kq * 68];
        ull ar0 = 0, ar1 = 0, az0 = 0, az1 = 0, an0 = 0, an1 = 0;
#pragma unroll
        for (int qq = 0; qq < 16; ++qq) {
            ulonglong2 hv2 = *(const ulonglong2*)(hp + qq * 4);
            ar0 = ffma2(Wr2[qq * 2],     hv2.x, ar0);
            ar1 = ffma2(Wr2[qq * 2 + 1], hv2.y, ar1);
            az0 = ffma2(Wz2[qq * 2],     hv2.x, az0);
            az1 = ffma2(Wz2[qq * 2 + 1], hv2.y, az1);
            an0 = ffma2(Wn2[qq * 2],     hv2.x, an0);
            an1 = ffma2(Wn2[qq * 2 + 1], hv2.y, an1);
        }
        float sr = sum2(fadd2(ar0, ar1));
        float sz = sum2(fadd2(az0, az1));
        float sn = sum2(fadd2(an0, an1));
#pragma unroll
        for (int m = 8; m <= 16; m <<= 1) {
            sr += __shfl_xor_sync(0xFFFFFFFFu, sr, m);
            sz += __shfl_xor_sync(0xFFFFFFFFu, sz, m);
            sn += __shfl_xor_sync(0xFFFFFFFFu, sn, m);
        }

        float gr = __shfl_sync(0xFFFFFFFFu, gv0, j);
        float gz = __shfl_sync(0xFFFFFFFFu, gv0, 8 + j);
        float gn = __shfl_sync(0xFFFFFFFFu, gv0, 16 + j);

        {
            float r = fast_sigmoid(gr + sr);
            float z = fast_sigmoid(gz + sz);
            float n = fast_tanh(fmaf(r, sn + bhn_u, gn));
            hprev = fmaf(z, hprev - n, n);
        }

        // 4. send: warp's 8 units to all 4 CTAs (8 lanes x 1 v4)
        if (s + 1 < T_) {
            const uint32_t qoff = (uint32_t)((s + 1) & 3) * 1088;
            const int base = (lane & 1) * 4;
            float4 v;
            v.x = __shfl_sync(0xFFFFFFFFu, hprev, base + 0);
            v.y = __shfl_sync(0xFFFFFFFFu, hprev, base + 1);
            v.z = __shfl_sync(0xFFFFFFFFu, hprev, base + 2);
            v.w = __shfl_sync(0xFFFFFFFFu, hprev, base + 3);
            if (lane < 8) {
                asm volatile("st.shared::cluster.v4.b32 [%0], {%1, %2, %3, %4};"
                             :: "r"(sdata + qoff),
                                "r"(__float_as_uint(v.x)), "r"(__float_as_uint(v.y)),
                                "r"(__float_as_uint(v.z)), "r"(__float_as_uint(v.w))
                             : "memory");
            }
            gv0 = gv1; gv1 = gv2;
            if (lane < 24 && s + 3 < T_) {
                const int tn = d ? (T_ - 4 - s) : (s + 3);
                gv2 = __ldg(xgp + (size_t)tn * G_ + lane);
            }
        }

        // 5. stage output
        if (lane < 8) hist[s & 15][w * 8 + lane] = hprev;

        // 6. skew-safe flush: rows [s-14, s-7]
        if ((s & 7) == 7) {
            const int rr = s - 14 + w;
            if (rr >= 0) {
                const int tw = d ? (T_ - 1 - rr) : rr;
                *(float2*)&g_outc[((size_t)b * T_ + tw) * 512 + d * 256 +
                                  rank * 64 + lane * 2] =
                    *(const float2*)&hist[rr & 15][lane * 2];
            }
        }
    }

    // tail rows 4089..4095
    __syncthreads();
    if (w >= 1) {
        const int rr = 4088 + w;
        const int tw = d ? (T_ - 1 - rr) : rr;
        *(float2*)&g_outc[((size_t)b * T_ + tw) * 512 + d * 256 +
                          rank * 64 + lane * 2] =
            *(const float2*)&hist[rr & 15][lane * 2];
    }

    asm volatile("barrier.cluster.arrive.aligned;" ::: "memory");
    asm volatile("barrier.cluster.wait.aligned;"   ::: "memory");
}

// ---------------------------------------------------------------------------
// Kernel C: heads. out_combined [32768,512] @ (Wm|Wv) [512,256] + bias.
// FFMA2, non-duplicated B, double-buffered, fast exp epilogue.
// ---------------------------------------------------------------------------
__global__ void __launch_bounds__(256) k_heads(
    const float* __restrict__ Wm, const float* __restrict__ bm,
    const float* __restrict__ Wv, const float* __restrict__ bv,
    float* __restrict__ out)
{
    const int n0 = blockIdx.x * 64;
    const int m0 = blockIdx.y * 128;
    const bool isV = (n0 >= 256);
    const float* W  = isV ? Wv : Wm;
    const float* bb = isV ? bv : bm;
    const int nw = n0 & 255;

    __shared__ __align__(16) float As[2][16][136];
    __shared__ __align__(16) float Bs[2][16][68];

    const int tid = threadIdx.x;
    const int ti = tid >> 4, tj = tid & 15;
    const int ar = tid >> 4, ac = tid & 15;
    const int br = tid >> 6, bc = tid & 63;

    ull acc2[4][4];
#pragma unroll
    for (int i = 0; i < 4; ++i)
#pragma unroll
        for (int j = 0; j < 4; ++j) acc2[i][j] = 0ull;

#pragma unroll
    for (int p = 0; p < 8; ++p)
        As[0][ac][ar + p * 16] = g_outc[(size_t)(m0 + ar + p * 16) * 512 + ac];
#pragma unroll
    for (int p = 0; p < 4; ++p)
        Bs[0][br + p * 4][bc] = W[(size_t)(br + p * 4) * 256 + nw + bc];
    __syncthreads();

    int buf = 0;
    for (int k0 = 0; k0 < 512; k0 += 16) {
        float xa[8], xb[4];
        if (k0 + 16 < 512) {
#pragma unroll
            for (int p = 0; p < 8; ++p)
                xa[p] = g_outc[(size_t)(m0 + ar + p * 16) * 512 + k0 + 16 + ac];
#pragma unroll
            for (int p = 0; p < 4; ++p)
                xb[p] = W[(size_t)(k0 + 16 + br + p * 4) * 256 + nw + bc];
        }
#pragma unroll
        for (int kk = 0; kk < 16; ++kk) {
            ull ap[4];
            const ull* arow = (const ull*)&As[buf][kk][ti * 8];
            ap[0] = arow[0]; ap[1] = arow[1]; ap[2] = arow[2]; ap[3] = arow[3];
            float4 bq = *(const float4*)&Bs[buf][kk][tj * 4];
            ull bd[4];
            bd[0] = dup2(bq.x); bd[1] = dup2(bq.y);
            bd[2] = dup2(bq.z); bd[3] = dup2(bq.w);
#pragma unroll
            for (int i = 0; i < 4; ++i)
#pragma unroll
                for (int jj = 0; jj < 4; ++jj)
                    acc2[i][jj] = ffma2(ap[i], bd[jj], acc2[i][jj]);
        }
        if (k0 + 16 < 512) {
#pragma unroll
            for (int p = 0; p < 8; ++p) As[buf ^ 1][ac][ar + p * 16] = xa[p];
#pragma unroll
            for (int p = 0; p < 4; ++p) Bs[buf ^ 1][br + p * 4][bc] = xb[p];
            __syncthreads();
            buf ^= 1;
        }
    }

    const size_t hofs = (size_t)M_ * H_;
    float4 bb4 = *(const float4*)&bb[nw + tj * 4];
#pragma unroll
    for (int i = 0; i < 4; ++i) {
        float4 o0, o1;
        unpack2(acc2[i][0], o0.x, o1.x);
        unpack2(acc2[i][1], o0.y, o1.y);
        unpack2(acc2[i][2], o0.z, o1.z);
        unpack2(acc2[i][3], o0.w, o1.w);
        o0.x += bb4.x; o0.y += bb4.y; o0.z += bb4.z; o0.w += bb4.w;
        o1.x += bb4.x; o1.y += bb4.y; o1.z += bb4.z; o1.w += bb4.w;
        int r0 = m0 + ti * 8 + i * 2, r1 = r0 + 1;
        if (isV) {
            o0.x = fast_exp(o0.x); o0.y = fast_exp(o0.y);
            o0.z = fast_exp(o0.z); o0.w = fast_exp(o0.w);
            o1.x = fast_exp(o1.x); o1.y = fast_exp(o1.y);
            o1.z = fast_exp(o1.z); o1.w = fast_exp(o1.w);
            *(float4*)&out[(size_t)r0 * 256 + nw + tj * 4] = o0;
            *(float4*)&out[(size_t)r1 * 256 + nw + tj * 4] = o1;
        } else {
            *(float4*)&out[hofs + (size_t)r0 * 256 + nw + tj * 4] = o0;
            *(float4*)&out[hofs + (size_t)r1 * 256 + nw + tj * 4] = o1;
        }
    }
}

// ---------------------------------------------------------------------------
extern "C" void kernel_launch(void* const* d_in, const int* in_sizes, int n_in,
                              void* d_out, int out_size)
{
    const float* inputs = (const float*)d_in[0];
    const float* Wi_f   = (const float*)d_in[1];
    const float* bi_f   = (const float*)d_in[2];
    const float* Wh_f   = (const float*)d_in[3];
    const float* bhn_f  = (const float*)d_in[4];
    const float* Wi_b   = (const float*)d_in[5];
    const float* bi_b   = (const float*)d_in[6];
    const float* Wh_b   = (const float*)d_in[7];
    const float* bhn_b  = (const float*)d_in[8];
    const float* Wm     = (const float*)d_in[9];
    const float* bm     = (const float*)d_in[10];
    const float* Wv     = (const float*)d_in[11];
    const float* bv     = (const float*)d_in[12];
    float* out = (float*)d_out;

    (void)in_sizes; (void)n_in; (void)out_size;

    // 1) reset counters + work queue
    k_init<<<1, 512>>>();
    // 2) fused producer/consumer: 16 scan clusters + 21 worker clusters
    k_mega<<<148, 256>>>(inputs, Wi_f, bi_f, Wi_b, bi_b,
                         Wh_f, bhn_f, Wh_b, bhn_b);
    // 3) heads: mean + exp(log-var)
    k_heads<<<dim3(8, 256), 256>>>(Wm, bm, Wv, bv, out);
}

// round 15
// speedup vs baseline: 1.7018x; 1.0888x over previous
#include <cuda_runtime.h>
#include <cstdint>

#define B_ 8
#define T_ 4096
#define D_ 256
#define H_ 256
#define G_ 768              // 3H
#define M_ (B_ * T_)        // 32768
#define CANARY 0x7FC00001u  // NaN pattern; h is always finite
#define NTILES 6144         // xgemm: 2 dirs x 256 m-tiles x 12 n-tiles
#define NHTILES 2048        // heads: 256 m-tiles x 8 n-blocks

// Scratch (static device allocations only)
// xg layout (scan-permuted): [d][b][t][rank(4)][w(8)][gate(3)][j(8)]
__device__ float g_xg[(size_t)2 * B_ * T_ * G_];
__device__ float g_outc[(size_t)B_ * T_ * 2 * H_];     // [b][t][512]  (fwd | bwd)
__device__ unsigned g_cnt[2 * 8 * 32];                 // [d][b][tc] xg tile counters
__device__ unsigned g_prog[2 * 8];                     // [d][b] scan progress (32/epoch)
__device__ unsigned g_tilectr;                         // xgemm work queue
__device__ unsigned g_headctr;                         // heads work queue

typedef unsigned long long ull;

__device__ __forceinline__ uint32_t s2u(const void* p) {
    uint32_t a;
    asm("{ .reg .u64 t; cvta.to.shared.u64 t, %1; cvt.u32.u64 %0, t; }"
        : "=r"(a) : "l"(p));
    return a;
}
__device__ __forceinline__ ull ffma2(ull a, ull b, ull c) {
    ull d;
    asm("fma.rn.f32x2 %0, %1, %2, %3;" : "=l"(d) : "l"(a), "l"(b), "l"(c));
    return d;
}
__device__ __forceinline__ ull fadd2(ull a, ull b) {
    ull d;
    asm("add.rn.f32x2 %0, %1, %2;" : "=l"(d) : "l"(a), "l"(b));
    return d;
}
__device__ __forceinline__ ull pack2(float lo, float hi) {
    ull r;
    asm("mov.b64 %0, {%1, %2};" : "=l"(r)
        : "r"(__float_as_uint(lo)), "r"(__float_as_uint(hi)));
    return r;
}
__device__ __forceinline__ ull dup2(float v) {
    ull r;
    asm("mov.b64 %0, {%1, %1};" : "=l"(r) : "r"(__float_as_uint(v)));
    return r;
}
__device__ __forceinline__ void unpack2(ull a, float& lo, float& hi) {
    uint32_t l, h;
    asm("mov.b64 {%0, %1}, %2;" : "=r"(l), "=r"(h) : "l"(a));
    lo = __uint_as_float(l); hi = __uint_as_float(h);
}
__device__ __forceinline__ float sum2(ull a) {
    float lo, hi; unpack2(a, lo, hi); return lo + hi;
}
__device__ __forceinline__ float fast_sigmoid(float x) {
    float e, r;
    asm("ex2.approx.f32 %0, %1;" : "=f"(e) : "f"(-1.4426950408889634f * x));
    asm("rcp.approx.f32 %0, %1;" : "=f"(r) : "f"(1.0f + e));
    return r;
}
__device__ __forceinline__ float fast_tanh(float x) {
    float e, r;
    asm("ex2.approx.f32 %0, %1;" : "=f"(e) : "f"(-2.8853900817779268f * x));
    asm("rcp.approx.f32 %0, %1;" : "=f"(r) : "f"(1.0f + e));
    return fmaf(2.0f, r, -1.0f);
}
__device__ __forceinline__ float fast_exp(float x) {
    float e;
    asm("ex2.approx.f32 %0, %1;" : "=f"(e) : "f"(1.4426950408889634f * x));
    return e;
}
__device__ __forceinline__ unsigned ldacq_g(const unsigned* p) {
    unsigned v;
    asm volatile("ld.acquire.gpu.global.u32 %0, [%1];" : "=r"(v) : "l"(p));
    return v;
}
__device__ __forceinline__ void wait_cnt12(const unsigned* p) {
    while (ldacq_g(p) < 12u) { }
}

// ---------------------------------------------------------------------------
// k_init: reset all counters (stream-ordered before k_mega).
// ---------------------------------------------------------------------------
__global__ void k_init() {
    int t = threadIdx.x;
    if (t < 512) g_cnt[t] = 0u;
    if (t < 16)  g_prog[t] = 0u;
    if (t == 0)  { g_tilectr = 0u; g_headctr = 0u; }
}

// ---------------------------------------------------------------------------
// One 128x64 xgemm tile (FFMA2, double-buffered), permuted store to g_xg.
// ---------------------------------------------------------------------------
__device__ __forceinline__ void gemm_tile(
    const float* __restrict__ X, const float* __restrict__ W,
    const float* __restrict__ bi, float* __restrict__ out,
    int m0, int n0,
    float (&As)[2][16][136], float (&Bs)[2][16][68])
{
    const int tid = threadIdx.x;
    const int ti = tid >> 4;
    const int tj = tid & 15;
    const int ar = tid >> 4, ac = tid & 15;
    const int br = tid >> 6, bc = tid & 63;

    ull acc2[4][4];
#pragma unroll
    for (int i = 0; i < 4; ++i)
#pragma unroll
        for (int j = 0; j < 4; ++j) acc2[i][j] = 0ull;

#pragma unroll
    for (int p = 0; p < 8; ++p)
        As[0][ac][ar + p * 16] = X[(size_t)(m0 + ar + p * 16) * D_ + ac];
#pragma unroll
    for (int p = 0; p < 4; ++p)
        Bs[0][br + p * 4][bc] = W[(size_t)(br + p * 4) * G_ + n0 + bc];
    __syncthreads();

    int buf = 0;
    for (int k0 = 0; k0 < D_; k0 += 16) {
        float xa[8], xb[4];
        if (k0 + 16 < D_) {
#pragma unroll
            for (int p = 0; p < 8; ++p)
                xa[p] = X[(size_t)(m0 + ar + p * 16) * D_ + k0 + 16 + ac];
#pragma unroll
            for (int p = 0; p < 4; ++p)
                xb[p] = W[(size_t)(k0 + 16 + br + p * 4) * G_ + n0 + bc];
        }
#pragma unroll
        for (int kk = 0; kk < 16; ++kk) {
            ull ap[4];
            const ull* arow = (const ull*)&As[buf][kk][ti * 8];
            ap[0] = arow[0]; ap[1] = arow[1]; ap[2] = arow[2]; ap[3] = arow[3];
            float4 bq = *(const float4*)&Bs[buf][kk][tj * 4];
            ull bd[4];
            bd[0] = dup2(bq.x); bd[1] = dup2(bq.y);
            bd[2] = dup2(bq.z); bd[3] = dup2(bq.w);
#pragma unroll
            for (int i = 0; i < 4; ++i)
#pragma unroll
                for (int j = 0; j < 4; ++j)
                    acc2[i][j] = ffma2(ap[i], bd[j], acc2[i][j]);
        }
        if (k0 + 16 < D_) {
#pragma unroll
            for (int p = 0; p < 8; ++p) As[buf ^ 1][ac][ar + p * 16] = xa[p];
#pragma unroll
            for (int p = 0; p < 4; ++p) Bs[buf ^ 1][br + p * 4][bc] = xb[p];
            __syncthreads();
            buf ^= 1;
        }
    }

    const int n = n0 + tj * 4;
    const int g = n >> 8, u = n & 255;
    const int pos = (u >> 6) * 192 + ((u >> 3) & 7) * 24 + g * 8 + (u & 7);
    float4 bb = *(const float4*)&bi[n];
#pragma unroll
    for (int i = 0; i < 4; ++i) {
        float4 o0, o1;
        unpack2(acc2[i][0], o0.x, o1.x);
        unpack2(acc2[i][1], o0.y, o1.y);
        unpack2(acc2[i][2], o0.z, o1.z);
        unpack2(acc2[i][3], o0.w, o1.w);
        o0.x += bb.x; o0.y += bb.y; o0.z += bb.z; o0.w += bb.w;
        o1.x += bb.x; o1.y += bb.y; o1.z += bb.z; o1.w += bb.w;
        *(float4*)&out[(size_t)(m0 + ti * 8 + i * 2)     * G_ + pos] = o0;
        *(float4*)&out[(size_t)(m0 + ti * 8 + i * 2 + 1) * G_ + pos] = o1;
    }
}

// ---------------------------------------------------------------------------
// One 128x64 heads tile (FFMA2, double-buffered, fast-exp epilogue).
// ---------------------------------------------------------------------------
__device__ __forceinline__ void heads_tile(
    const float* __restrict__ W, const float* __restrict__ bbp, bool isV,
    int m0, int nw, float* __restrict__ out,
    float (&As)[2][16][136], float (&Bs)[2][16][68])
{
    const int tid = threadIdx.x;
    const int ti = tid >> 4, tj = tid & 15;
    const int ar = tid >> 4, ac = tid & 15;
    const int br = tid >> 6, bc = tid & 63;

    ull acc2[4][4];
#pragma unroll
    for (int i = 0; i < 4; ++i)
#pragma unroll
        for (int j = 0; j < 4; ++j) acc2[i][j] = 0ull;

#pragma unroll
    for (int p = 0; p < 8; ++p)
        As[0][ac][ar + p * 16] = g_outc[(size_t)(m0 + ar + p * 16) * 512 + ac];
#pragma unroll
    for (int p = 0; p < 4; ++p)
        Bs[0][br + p * 4][bc] = W[(size_t)(br + p * 4) * 256 + nw + bc];
    __syncthreads();

    int buf = 0;
    for (int k0 = 0; k0 < 512; k0 += 16) {
        float xa[8], xb[4];
        if (k0 + 16 < 512) {
#pragma unroll
            for (int p = 0; p < 8; ++p)
                xa[p] = g_outc[(size_t)(m0 + ar + p * 16) * 512 + k0 + 16 + ac];
#pragma unroll
            for (int p = 0; p < 4; ++p)
                xb[p] = W[(size_t)(k0 + 16 + br + p * 4) * 256 + nw + bc];
        }
#pragma unroll
        for (int kk = 0; kk < 16; ++kk) {
            ull ap[4];
            const ull* arow = (const ull*)&As[buf][kk][ti * 8];
            ap[0] = arow[0]; ap[1] = arow[1]; ap[2] = arow[2]; ap[3] = arow[3];
            float4 bq = *(const float4*)&Bs[buf][kk][tj * 4];
            ull bd[4];
            bd[0] = dup2(bq.x); bd[1] = dup2(bq.y);
            bd[2] = dup2(bq.z); bd[3] = dup2(bq.w);
#pragma unroll
            for (int i = 0; i < 4; ++i)
#pragma unroll
                for (int jj = 0; jj < 4; ++jj)
                    acc2[i][jj] = ffma2(ap[i], bd[jj], acc2[i][jj]);
        }
        if (k0 + 16 < 512) {
#pragma unroll
            for (int p = 0; p < 8; ++p) As[buf ^ 1][ac][ar + p * 16] = xa[p];
#pragma unroll
            for (int p = 0; p < 4; ++p) Bs[buf ^ 1][br + p * 4][bc] = xb[p];
            __syncthreads();
            buf ^= 1;
        }
    }

    const size_t hofs = (size_t)M_ * H_;
    float4 bb4 = *(const float4*)&bbp[nw + tj * 4];
#pragma unroll
    for (int i = 0; i < 4; ++i) {
        float4 o0, o1;
        unpack2(acc2[i][0], o0.x, o1.x);
        unpack2(acc2[i][1], o0.y, o1.y);
        unpack2(acc2[i][2], o0.z, o1.z);
        unpack2(acc2[i][3], o0.w, o1.w);
        o0.x += bb4.x; o0.y += bb4.y; o0.z += bb4.z; o0.w += bb4.w;
        o1.x += bb4.x; o1.y += bb4.y; o1.z += bb4.z; o1.w += bb4.w;
        int r0 = m0 + ti * 8 + i * 2, r1 = r0 + 1;
        if (isV) {
            o0.x = fast_exp(o0.x); o0.y = fast_exp(o0.y);
            o0.z = fast_exp(o0.z); o0.w = fast_exp(o0.w);
            o1.x = fast_exp(o1.x); o1.y = fast_exp(o1.y);
            o1.z = fast_exp(o1.z); o1.w = fast_exp(o1.w);
            *(float4*)&out[(size_t)r0 * 256 + nw + tj * 4] = o0;
            *(float4*)&out[(size_t)r1 * 256 + nw + tj * 4] = o1;
        } else {
            *(float4*)&out[hofs + (size_t)r0 * 256 + nw + tj * 4] = o0;
            *(float4*)&out[hofs + (size_t)r1 * 256 + nw + tj * 4] = o1;
        }
    }
}

// ---------------------------------------------------------------------------
// heads_loop: pull heads tiles (unlock-epoch priority order), wait on scan
// progress counters, compute. Entered by workers (after xgemm queue drains)
// and by scan CTAs after the scan completes.
// ---------------------------------------------------------------------------
__device__ void heads_loop(
    const float* Wm, const float* bm, const float* Wv, const float* bv,
    float* out, float (&As)[2][16][136], float (&Bs)[2][16][68], int* s_idx)
{
    const int tid = threadIdx.x;
    for (;;) {
        if (tid == 0) *s_idx = (int)atomicAdd(&g_headctr, 1u);
        __syncthreads();
        const int hidx = *s_idx;
        if (hidx >= NHTILES) break;

        // priority decode: pair k unlocks at epoch 18+k; tc = 15-k or 16+k
        const int k   = hidx >> 7;
        const int sub = hidx & 127;
        const int tc  = (sub & 1) ? (16 + k) : (15 - k);
        const int b   = (sub >> 1) & 7;
        const int nb  = sub >> 4;                 // 0..7
        const int m0  = (b * 32 + tc) * 128;
        const int n0  = nb * 64;
        const bool isV = (n0 >= 256);
        const int nw  = n0 & 255;

        // readiness: fwd epoch tc+2, bwd epoch 33-tc (tc=0 -> 33)
        const unsigned ef = (unsigned)(tc + 2);
        const unsigned eb = (unsigned)((tc == 0) ? 33 : (33 - tc));
        if (tid == 0) {
            const unsigned* pf = &g_prog[b];
            const unsigned* pb = &g_prog[8 + b];
            while (ldacq_g(pf) < 32u * ef) __nanosleep(256);
            while (ldacq_g(pb) < 32u * eb) __nanosleep(256);
        }
        __syncthreads();

        heads_tile(isV ? Wv : Wm, isV ? bv : bm, isV, m0, nw, out, As, Bs);
    }
}

// ---------------------------------------------------------------------------
// k_mega: 37 clusters x 4 CTAs.
//   blockIdx 0..63  : GRU scan (frozen protocol) + progress publishing,
//                     then joins the heads queue.
//   blockIdx 64..147: xgemm workers -> heads workers.
// ---------------------------------------------------------------------------
__global__ void __launch_bounds__(256, 1) __cluster_dims__(4, 1, 1)
k_mega(const float* __restrict__ X,
       const float* __restrict__ Wi_f, const float* __restrict__ bi_f,
       const float* __restrict__ Wi_b, const float* __restrict__ bi_b,
       const float* __restrict__ Wh_f, const float* __restrict__ bhn_f,
       const float* __restrict__ Wh_b, const float* __restrict__ bhn_b,
       const float* __restrict__ Wm, const float* __restrict__ bm,
       const float* __restrict__ Wv, const float* __restrict__ bv,
       float* __restrict__ out)
{
    __shared__ __align__(16) float As[2][16][136];   // gemm/heads tiles
    __shared__ __align__(16) float Bs[2][16][68];
    __shared__ __align__(16) float hbuf[4][272];     // scan ring
    __shared__ __align__(16) float hist[16][64];     // scan output staging
    __shared__ int s_idx;

    const int tid = threadIdx.x;

    if (blockIdx.x >= 64) {
        // ================= WORKER PATH =================
        for (;;) {
            if (tid == 0) s_idx = (int)atomicAdd(&g_tilectr, 1u);
            __syncthreads();
            const int idx = s_idx;
            if (idx >= NTILES) break;

            const int k  = idx / 96;
            const int r  = idx - k * 96;
            const int bb = r / 12;
            const int bx = r - bb * 12;
            const int dd = k & 1;
            const int ii = k >> 1;
            const int tc = dd ? (31 - ii) : ii;
            const int m0 = (bb * 32 + tc) * 128;
            const int n0 = bx * 64;

            gemm_tile(X, dd ? Wi_b : Wi_f, dd ? bi_b : bi_f,
                      g_xg + (size_t)dd * M_ * G_, m0, n0, As, Bs);

            __threadfence();
            __syncthreads();
            if (tid == 0) {
                const unsigned* p = &g_cnt[(dd * 8 + bb) * 32 + tc];
                asm volatile("red.release.gpu.global.add.u32 [%0], %1;"
                             :: "l"(p), "r"(1u) : "memory");
            }
        }
        // xgemm drained -> heads
        heads_loop(Wm, bm, Wv, bv, out, As, Bs, &s_idx);
        return;
    }

    // ================= SCAN PATH (frozen protocol) =================
    const uint32_t hbuf_a = s2u(hbuf);

    const int rank = blockIdx.x & 3;
    const int cid  = blockIdx.x >> 2;
    const int d    = cid >> 3;
    const int b    = cid & 7;

    const float* Wh  = d ? Wh_b  : Wh_f;
    const float* bhn = d ? bhn_b : bhn_f;

    const int w    = tid >> 5;
    const int lane = tid & 31;
    const int kq   = lane >> 3;
    const int j    = lane & 7;
    const int unit = rank * 64 + w * 8 + j;
    const unsigned* cbase = &g_cnt[(d * 8 + b) * 32];
    unsigned* prog = &g_prog[d * 8 + b];

    ull Wr2[32], Wz2[32], Wn2[32];
#pragma unroll
    for (int kk = 0; kk < 32; ++kk) {
        size_t r0 = (size_t)(kq * 64 + kk * 2) * G_;
        size_t r1 = r0 + G_;
        Wr2[kk] = pack2(__ldg(Wh + r0 + unit),       __ldg(Wh + r1 + unit));
        Wz2[kk] = pack2(__ldg(Wh + r0 + 256 + unit), __ldg(Wh + r1 + 256 + unit));
        Wn2[kk] = pack2(__ldg(Wh + r0 + 512 + unit), __ldg(Wh + r1 + 512 + unit));
    }

    for (int i = tid; i < 272; i += 256) {
        hbuf[0][i] = 0.f;
        ((unsigned*)hbuf[1])[i] = CANARY;
        ((unsigned*)hbuf[2])[i] = CANARY;
        ((unsigned*)hbuf[3])[i] = CANARY;
    }
    __syncthreads();
    asm volatile("barrier.cluster.arrive.aligned;" ::: "memory");
    asm volatile("barrier.cluster.wait.aligned;"   ::: "memory");

    uint32_t sdata = 0;
    if (lane < 8) {
        uint32_t peer = (uint32_t)((rank + (lane >> 1)) & 3);
        uint32_t rhb;
        asm("mapa.shared::cluster.u32 %0, %1, %2;" : "=r"(rhb) : "r"(hbuf_a), "r"(peer));
        sdata = rhb + (uint32_t)(rank * 272 + w * 32 + (lane & 1) * 16);
    }
    const uint32_t pa = hbuf_a + (uint32_t)(kq * 272 + j * 32);
    const uint32_t ca = hbuf_a + (uint32_t)((w >> 1) * 272 + (w & 1) * 128 + lane * 4);

    const float bhn_u = bhn[unit];
    const float* xgp = g_xg + ((size_t)(d * B_ + b)) * T_ * G_ + rank * 192 + w * 24;

    wait_cnt12(cbase + (d ? 31 : 0));
    wait_cnt12(cbase + (d ? 30 : 1));

    float gv0 = 0.f, gv1 = 0.f, gv2 = 0.f;
    if (lane < 24) {
        gv0 = __ldg(xgp + (size_t)(d ? T_ - 1 : 0) * G_ + lane);
        gv1 = __ldg(xgp + (size_t)(d ? T_ - 2 : 1) * G_ + lane);
        gv2 = __ldg(xgp + (size_t)(d ? T_ - 3 : 2) * G_ + lane);
    }

    float hprev = 0.f;

    for (int s = 0; s < T_; ++s) {
        const int q = s & 3;

        if ((s & 127) == 0 && s) {
            const int a = s >> 7;
            const int c0 = d ? (31 - a) : a;
            const int c1n = (a < 31) ? (a + 1) : 31;
            const int c1 = d ? (31 - c1n) : c1n;
            wait_cnt12(cbase + c0);
            wait_cnt12(cbase + c1);
        }

        // 1. poll canary
        {
            const uint32_t a = pa + (uint32_t)q * 1088;
            for (;;) {
                uint32_t x0, x1, x2, x3, y0, y1, y2, y3;
                asm volatile("ld.volatile.shared.v4.u32 {%0,%1,%2,%3}, [%4];"
                             : "=r"(x0), "=r"(x1), "=r"(x2), "=r"(x3) : "r"(a));
                asm volatile("ld.volatile.shared.v4.u32 {%0,%1,%2,%3}, [%4];"
                             : "=r"(y0), "=r"(y1), "=r"(y2), "=r"(y3) : "r"(a + 16));
                bool bad = (x0 == CANARY) | (x1 == CANARY) | (x2 == CANARY) |
                           (x3 == CANARY) | (y0 == CANARY) | (y1 == CANARY) |
                           (y2 == CANARY) | (y3 == CANARY);
                if (!__any_sync(0xFFFFFFFFu, bad)) break;
            }
        }

        // 2. re-canary buf (q+2)&3
        {
            const uint32_t a = ca + (uint32_t)((q + 2) & 3) * 1088;
            asm volatile("st.shared.u32 [%0], %1;" :: "r"(a), "r"(CANARY) : "memory");
        }

        // 3. dots
        const float* hp = &hbuf[q][kq * 68];
        ull ar0 = 0, ar1 = 0, az0 = 0, az1 = 0, an0 = 0, an1 = 0;
#pragma unroll
        for (int qq = 0; qq < 16; ++qq) {
            ulonglong2 hv2 = *(const ulonglong2*)(hp + qq * 4);
            ar0 = ffma2(Wr2[qq * 2],     hv2.x, ar0);
            ar1 = ffma2(Wr2[qq * 2 + 1], hv2.y, ar1);
            az0 = ffma2(Wz2[qq * 2],     hv2.x, az0);
            az1 = ffma2(Wz2[qq * 2 + 1], hv2.y, az1);
            an0 = ffma2(Wn2[qq * 2],     hv2.x, an0);
            an1 = ffma2(Wn2[qq * 2 + 1], hv2.y, an1);
        }
        float sr = sum2(fadd2(ar0, ar1));
        float sz = sum2(fadd2(az0, az1));
        float sn = sum2(fadd2(an0, an1));
#pragma unroll
        for (int m = 8; m <= 16; m <<= 1) {
            sr += __shfl_xor_sync(0xFFFFFFFFu, sr, m);
            sz += __shfl_xor_sync(0xFFFFFFFFu, sz, m);
            sn += __shfl_xor_sync(0xFFFFFFFFu, sn, m);
        }

        float gr = __shfl_sync(0xFFFFFFFFu, gv0, j);
        float gz = __shfl_sync(0xFFFFFFFFu, gv0, 8 + j);
        float gn = __shfl_sync(0xFFFFFFFFu, gv0, 16 + j);

        {
            float r = fast_sigmoid(gr + sr);
            float z = fast_sigmoid(gz + sz);
            float n = fast_tanh(fmaf(r, sn + bhn_u, gn));
            hprev = fmaf(z, hprev - n, n);
        }

        // 4. send
        if (s + 1 < T_) {
            const uint32_t qoff = (uint32_t)((s + 1) & 3) * 1088;
            const int base = (lane & 1) * 4;
            float4 v;
            v.x = __shfl_sync(0xFFFFFFFFu, hprev, base + 0);
            v.y = __shfl_sync(0xFFFFFFFFu, hprev, base + 1);
            v.z = __shfl_sync(0xFFFFFFFFu, hprev, base + 2);
            v.w = __shfl_sync(0xFFFFFFFFu, hprev, base + 3);
            if (lane < 8) {
                asm volatile("st.shared::cluster.v4.b32 [%0], {%1, %2, %3, %4};"
                             :: "r"(sdata + qoff),
                                "r"(__float_as_uint(v.x)), "r"(__float_as_uint(v.y)),
                                "r"(__float_as_uint(v.z)), "r"(__float_as_uint(v.w))
                             : "memory");
            }
            gv0 = gv1; gv1 = gv2;
            if (lane < 24 && s + 3 < T_) {
                const int tn = d ? (T_ - 4 - s) : (s + 3);
                gv2 = __ldg(xgp + (size_t)tn * G_ + lane);
            }
        }

        // 5. stage output
        if (lane < 8) hist[s & 15][w * 8 + lane] = hprev;

        // 6. skew-safe flush + progress publish (per warp, every 128 steps)
        if ((s & 7) == 7) {
            const int rr = s - 14 + w;
            if (rr >= 0) {
                const int tw = d ? (T_ - 1 - rr) : rr;
                *(float2*)&g_outc[((size_t)b * T_ + tw) * 512 + d * 256 +
                                  rank * 64 + lane * 2] =
                    *(const float2*)&hist[rr & 15][lane * 2];
            }
            if ((s & 127) == 127 && lane == 0) {
                __threadfence();
                asm volatile("red.release.gpu.global.add.u32 [%0], %1;"
                             :: "l"(prog), "r"(1u) : "memory");
            }
        }
    }

    // tail rows 4089..4095
    __syncthreads();
    if (w >= 1) {
        const int rr = 4088 + w;
        const int tw = d ? (T_ - 1 - rr) : rr;
        *(float2*)&g_outc[((size_t)b * T_ + tw) * 512 + d * 256 +
                          rank * 64 + lane * 2] =
            *(const float2*)&hist[rr & 15][lane * 2];
    }
    // epoch 33 publish (each warp orders its own stores)
    if (lane == 0) {
        __threadfence();
        asm volatile("red.release.gpu.global.add.u32 [%0], %1;"
                     :: "l"(prog), "r"(1u) : "memory");
    }

    asm volatile("barrier.cluster.arrive.aligned;" ::: "memory");
    asm volatile("barrier.cluster.wait.aligned;"   ::: "memory");

    // scan done -> help drain heads queue
    heads_loop(Wm, bm, Wv, bv, out, As, Bs, &s_idx);
}

// ---------------------------------------------------------------------------
extern "C" void kernel_launch(void* const* d_in, const int* in_sizes, int n_in,
                              void* d_out, int out_size)
{
    const float* inputs = (const float*)d_in[0];
    const float* Wi_f   = (const float*)d_in[1];
    const float* bi_f   = (const float*)d_in[2];
    const float* Wh_f   = (const float*)d_in[3];
    const float* bhn_f  = (const float*)d_in[4];
    const float* Wi_b   = (const float*)d_in[5];
    const float* bi_b   = (const float*)d_in[6];
    const float* Wh_b   = (const float*)d_in[7];
    const float* bhn_b  = (const float*)d_in[8];
    const float* Wm     = (const float*)d_in[9];
    const float* bm     = (const float*)d_in[10];
    const float* Wv     = (const float*)d_in[11];
    const float* bv     = (const float*)d_in[12];
    float* out = (float*)d_out;

    (void)in_sizes; (void)n_in; (void)out_size;

    // 1) reset counters + work queues
    k_init<<<1, 512>>>();
    // 2) fully fused: xgemm workers + scan + heads, one launch
    k_mega<<<148, 256>>>(inputs, Wi_f, bi_f, Wi_b, bi_b,
                         Wh_f, bhn_f, Wh_b, bhn_b,
                         Wm, bm, Wv, bv, out);
}